// round 10
// baseline (speedup 1.0000x reference)
#include <cuda_runtime.h>
#include <cuda_bf16.h>
#include <cstdint>

// Problem dims
#define NUM_NODES 1000000
#define HIDDEN    128
#define OUT_DIM   64
#define FANOUT    16
#define N_SRC0    1048576
#define N_DST0    65536
#define N_DST1    4096

// ---------------- scratch (static device globals; no allocations) ----------
__device__ uint32_t g_X0[(size_t)N_DST0 * 256];   // tf32 BITS [self|mean]
__device__ float    g_H1[(size_t)N_DST0 * 128];   // layer-0 output (post-ReLU)
__device__ float    g_X1[(size_t)N_DST1 * 256];   // [self | mean] per dst1 row
__device__ uint32_t g_W0T[256 * 128];             // tf32 BITS: [k][n] = cat(Ws0,Wn0)^T
__device__ float    g_b0[128];                    // b_self0 + b_neigh0
__device__ float    g_WfT[256 * 64];              // [k][n] = (W_out @ cat(Ws1,Wn1))^T
__device__ float    g_bf[64];                     // W_out @ (bs1+bn1) + b_out

// ---------------- helpers --------------------------------------------------
__device__ __forceinline__ uint32_t f2tf32(float f) {
    uint32_t r; asm("cvt.rna.tf32.f32 %0, %1;" : "=r"(r) : "f"(f)); return r;
}

__device__ __forceinline__ float4 f4add(float4 a, float4 b) {
    return make_float4(a.x + b.x, a.y + b.y, a.z + b.z, a.w + b.w);
}

__device__ __forceinline__ uint32_t smem_u32(const void* p) {
    uint32_t a;
    asm("{ .reg .u64 t; cvta.to.shared.u64 t, %1; cvt.u32.u64 %0, t; }" : "=r"(a) : "l"(p));
    return a;
}

__device__ __forceinline__ void mma_tf32(float c[4],
                                         uint32_t a0, uint32_t a1, uint32_t a2, uint32_t a3,
                                         uint32_t b0, uint32_t b1) {
    asm volatile(
        "mma.sync.aligned.m16n8k8.row.col.f32.tf32.tf32.f32 "
        "{%0,%1,%2,%3}, {%4,%5,%6,%7}, {%8,%9}, {%0,%1,%2,%3};"
        : "+f"(c[0]), "+f"(c[1]), "+f"(c[2]), "+f"(c[3])
        : "r"(a0), "r"(a1), "r"(a2), "r"(a3), "r"(b0), "r"(b1));
}

// ---------------- prep (merged): W0 pack + layer1/out fusion ---------------
__global__ void prep_all(const float* __restrict__ Ws0, const float* __restrict__ bs0,
                         const float* __restrict__ Wn0, const float* __restrict__ bn0,
                         const float* __restrict__ Ws1, const float* __restrict__ bs1,
                         const float* __restrict__ Wn1, const float* __restrict__ bn1,
                         const float* __restrict__ Wout, const float* __restrict__ bout) {
    if (blockIdx.x < 128) {
        int idx = blockIdx.x * 256 + threadIdx.x;       // 0..32767
        int k = idx >> 7;
        int n = idx & 127;
        float v = (k < 128) ? Ws0[n * 128 + k] : Wn0[n * 128 + (k - 128)];
        g_W0T[idx] = f2tf32(v);
        if (idx < 128) g_b0[idx] = bs0[idx] + bn0[idx];
    } else {
        int idx = (blockIdx.x - 128) * 256 + threadIdx.x;   // 0..16383
        int k = idx >> 6;
        int n = idx & 63;
        float acc = 0.f;
        if (k < 128) {
            #pragma unroll 4
            for (int r = 0; r < 128; r++) acc += Wout[n * 128 + r] * Ws1[r * 128 + k];
        } else {
            int kk = k - 128;
            #pragma unroll 4
            for (int r = 0; r < 128; r++) acc += Wout[n * 128 + r] * Wn1[r * 128 + kk];
        }
        g_WfT[k * 64 + n] = acc;
        if (idx < 64) {
            float a2 = bout[idx];
            #pragma unroll 4
            for (int r = 0; r < 128; r++) a2 += Wout[idx * 128 + r] * (bs1[r] + bn1[r]);
            g_bf[idx] = a2;
        }
    }
}

// ---------------- layer-0 gather: register-batched loads (proven) ----------
__global__ __launch_bounds__(256, 4) void gather0_kernel(
    const float* __restrict__ emb, const int* __restrict__ input_nodes,
    const int* __restrict__ nbr0) {
    __shared__ int s_idx[64 * FANOUT];
    __shared__ int s_self[64];

    const int tid  = threadIdx.x;
    const int lane = tid & 31;
    const int wid  = tid >> 5;
    const int base = blockIdx.x * 64;

    #pragma unroll
    for (int it = 0; it < 4; it++) {
        int i = it * 256 + tid;
        s_idx[i] = input_nodes[nbr0[(size_t)base * FANOUT + i]];
    }
    if (tid < 64) s_self[tid] = input_nodes[base + tid];
    __syncthreads();

    const float4* E = (const float4*)emb;        // row stride = 32 float4
    const float inv = 1.0f / (float)FANOUT;

    #pragma unroll 2
    for (int rr = 0; rr < 8; rr++) {
        const int r = wid * 8 + rr;

        int gj[FANOUT];
        #pragma unroll
        for (int j = 0; j < FANOUT; j++) gj[j] = s_idx[r * FANOUT + j];
        const int gs = s_self[r];

        float4 v0 = __ldg(&E[(size_t)gs * 32 + lane]);
        float4 n0 = __ldg(&E[(size_t)gj[0] * 32 + lane]);
        float4 n1 = __ldg(&E[(size_t)gj[1] * 32 + lane]);
        float4 n2 = __ldg(&E[(size_t)gj[2] * 32 + lane]);
        float4 n3 = __ldg(&E[(size_t)gj[3] * 32 + lane]);
        float4 n4 = __ldg(&E[(size_t)gj[4] * 32 + lane]);
        float4 n5 = __ldg(&E[(size_t)gj[5] * 32 + lane]);
        float4 n6 = __ldg(&E[(size_t)gj[6] * 32 + lane]);
        float4 n7 = __ldg(&E[(size_t)gj[7] * 32 + lane]);
        float4 t0 = f4add(n0, n1), t1 = f4add(n2, n3);
        float4 t2 = f4add(n4, n5), t3 = f4add(n6, n7);
        float4 acc1 = f4add(f4add(t0, t1), f4add(t2, t3));

        float4 m0 = __ldg(&E[(size_t)gj[8]  * 32 + lane]);
        float4 m1 = __ldg(&E[(size_t)gj[9]  * 32 + lane]);
        float4 m2 = __ldg(&E[(size_t)gj[10] * 32 + lane]);
        float4 m3 = __ldg(&E[(size_t)gj[11] * 32 + lane]);
        float4 m4 = __ldg(&E[(size_t)gj[12] * 32 + lane]);
        float4 m5 = __ldg(&E[(size_t)gj[13] * 32 + lane]);
        float4 m6 = __ldg(&E[(size_t)gj[14] * 32 + lane]);
        float4 m7 = __ldg(&E[(size_t)gj[15] * 32 + lane]);
        float4 u0 = f4add(m0, m1), u1 = f4add(m2, m3);
        float4 u2 = f4add(m4, m5), u3 = f4add(m6, m7);
        float4 acc2 = f4add(f4add(u0, u1), f4add(u2, u3));

        float4 acc = f4add(acc1, acc2);

        uint4 ts, tn;
        ts.x = f2tf32(v0.x); ts.y = f2tf32(v0.y); ts.z = f2tf32(v0.z); ts.w = f2tf32(v0.w);
        tn.x = f2tf32(acc.x * inv); tn.y = f2tf32(acc.y * inv);
        tn.z = f2tf32(acc.z * inv); tn.w = f2tf32(acc.w * inv);
        size_t row = (size_t)base + r;
        *(uint4*)&g_X0[row * 256 + lane * 4]       = ts;
        *(uint4*)&g_X0[row * 256 + 128 + lane * 4] = tn;
    }
}

// ---------------- gemm0: tf32 MMA, 3-stage cp.async, 1 sync/iter -----------
// g_H1 = relu(X0 @ W0T + b0).  M=65536, N=128, K=256. 128x128 CTA tile,
// BK=32, 8 warps 2(m) x 4(n).
#define AS_W (128 * 36)
#define BS_W (32 * 132)
#define STG_W (AS_W + BS_W)                       // 8832 words per stage
#define GEMM0_SM_BYTES (3 * STG_W * 4)            // 105984

__global__ __launch_bounds__(256, 2) void gemm0_tc_kernel() {
    extern __shared__ uint32_t sm[];

    const int tid  = threadIdx.x;
    const int l    = tid & 31;
    const int lm   = l >> 2;
    const int lk   = l & 3;
    const int wid  = tid >> 5;
    const int wm   = wid >> 2;
    const int wn   = wid & 3;
    const size_t block_row = (size_t)blockIdx.x * 128;
    const uint32_t* __restrict__ A = g_X0 + block_row * 256;
    const uint32_t* __restrict__ B = g_W0T;

    auto stageA = [&](int s) -> uint32_t (*)[36] {
        return (uint32_t (*)[36])(sm + s * STG_W);
    };
    auto stageB = [&](int s) -> uint32_t (*)[132] {
        return (uint32_t (*)[132])(sm + s * STG_W + AS_W);
    };

    auto prefetch = [&](int chunk) {
        const int s = chunk % 3;
        const int k0 = chunk * 32;
        uint32_t (*As)[36] = stageA(s);
        uint32_t (*Bs)[132] = stageB(s);
        #pragma unroll
        for (int it = 0; it < 4; it++) {
            int idx = it * 256 + tid;
            int row = idx >> 3;
            int c4  = idx & 7;
            uint32_t d = smem_u32(&As[row][c4 * 4]);
            const uint32_t* src = A + (size_t)row * 256 + k0 + c4 * 4;
            asm volatile("cp.async.cg.shared.global [%0], [%1], 16;" :: "r"(d), "l"(src));
        }
        #pragma unroll
        for (int it = 0; it < 4; it++) {
            int idx = it * 256 + tid;
            int kk = idx >> 5;
            int n4 = idx & 31;
            uint32_t d = smem_u32(&Bs[kk][n4 * 4]);
            const uint32_t* src = B + (size_t)(k0 + kk) * 128 + n4 * 4;
            asm volatile("cp.async.cg.shared.global [%0], [%1], 16;" :: "r"(d), "l"(src));
        }
        asm volatile("cp.async.commit_group;" ::: "memory");
    };

    float acc[4][4][4];
    #pragma unroll
    for (int i = 0; i < 4; i++)
        #pragma unroll
        for (int j = 0; j < 4; j++)
            #pragma unroll
            for (int c = 0; c < 4; c++) acc[i][j][c] = 0.f;

    prefetch(0);
    prefetch(1);

    #pragma unroll
    for (int ch = 0; ch < 8; ch++) {
        const int s = ch % 3;
        if (ch < 7) {
            asm volatile("cp.async.wait_group 1;" ::: "memory");
        } else {
            asm volatile("cp.async.wait_group 0;" ::: "memory");
        }
        __syncthreads();
        if (ch + 2 < 8) prefetch(ch + 2);   // writes buffer (ch+2)%3 — free

        uint32_t (*As)[36] = stageA(s);
        uint32_t (*Bs)[132] = stageB(s);
        #pragma unroll
        for (int kk = 0; kk < 4; kk++) {
            const int k8 = kk * 8;
            uint32_t af[4][4], bf[4][2];
            #pragma unroll
            for (int mt = 0; mt < 4; mt++) {
                int mrow = wm * 64 + mt * 16 + lm;
                af[mt][0] = As[mrow    ][k8 + lk];
                af[mt][1] = As[mrow + 8][k8 + lk];
                af[mt][2] = As[mrow    ][k8 + lk + 4];
                af[mt][3] = As[mrow + 8][k8 + lk + 4];
            }
            #pragma unroll
            for (int nt = 0; nt < 4; nt++) {
                int ncol = wn * 32 + nt * 8 + lm;
                bf[nt][0] = Bs[k8 + lk    ][ncol];
                bf[nt][1] = Bs[k8 + lk + 4][ncol];
            }
            #pragma unroll
            for (int mt = 0; mt < 4; mt++)
                #pragma unroll
                for (int nt = 0; nt < 4; nt++)
                    mma_tf32(acc[mt][nt], af[mt][0], af[mt][1], af[mt][2], af[mt][3],
                             bf[nt][0], bf[nt][1]);
        }
    }

    float2* __restrict__ H2 = (float2*)g_H1;      // row stride = 64 float2
    #pragma unroll
    for (int nt = 0; nt < 4; nt++) {
        int col = wn * 32 + nt * 8 + lk * 2;
        float bv0 = g_b0[col], bv1 = g_b0[col + 1];
        #pragma unroll
        for (int mt = 0; mt < 4; mt++) {
            size_t row0 = block_row + wm * 64 + mt * 16 + lm;
            float2 v0 = make_float2(fmaxf(acc[mt][nt][0] + bv0, 0.f),
                                    fmaxf(acc[mt][nt][1] + bv1, 0.f));
            float2 v1 = make_float2(fmaxf(acc[mt][nt][2] + bv0, 0.f),
                                    fmaxf(acc[mt][nt][3] + bv1, 0.f));
            H2[row0 * 64 + (col >> 1)]       = v0;
            H2[(row0 + 8) * 64 + (col >> 1)] = v1;
        }
    }
}

// ---------------- layer-1 gather: build X1 [N_DST1, 256] from g_H1 ---------
__global__ __launch_bounds__(256) void gather1_kernel(const int* __restrict__ nbr1) {
    int warp = (blockIdx.x * blockDim.x + threadIdx.x) >> 5;
    int lane = threadIdx.x & 31;
    if (warp >= N_DST1) return;

    int nj = 0;
    if (lane < FANOUT) nj = nbr1[warp * FANOUT + lane];

    const float4* H = (const float4*)g_H1;                // row stride = 32 float4
    float4 s = H[(size_t)warp * 32 + lane];
    float ax = 0.f, ay = 0.f, az = 0.f, aw = 0.f;
    #pragma unroll
    for (int j = 0; j < FANOUT; j++) {
        int g = __shfl_sync(0xffffffffu, nj, j);
        float4 v = H[(size_t)g * 32 + lane];
        ax += v.x; ay += v.y; az += v.z; aw += v.w;
    }
    const float inv = 1.0f / (float)FANOUT;
    float4* X = (float4*)g_X1;
    X[(size_t)warp * 64 + lane]      = s;
    X[(size_t)warp * 64 + 32 + lane] = make_float4(ax * inv, ay * inv, az * inv, aw * inv);
}

// ---------------- gemm1: out = g_X1 @ g_WfT + g_bf -------------------------
__global__ __launch_bounds__(256) void gemm1_kernel(float* __restrict__ C) {
    __shared__ float Bs[64][65];
    int tid = threadIdx.x;
    int r = blockIdx.x * 4 + (tid >> 6);
    int n = tid & 63;
    float acc = g_bf[n];
    for (int k0 = 0; k0 < 256; k0 += 64) {
        for (int i = tid; i < 64 * 64; i += 256)
            Bs[i >> 6][i & 63] = g_WfT[(size_t)(k0 + (i >> 6)) * 64 + (i & 63)];
        __syncthreads();
        const float* Ar = g_X1 + (size_t)r * 256 + k0;
        #pragma unroll 16
        for (int k = 0; k < 64; k++) acc = fmaf(Ar[k], Bs[k][n], acc);
        __syncthreads();
    }
    C[(size_t)r * 64 + n] = acc;
}

// ---------------- launch ---------------------------------------------------
extern "C" void kernel_launch(void* const* d_in, const int* in_sizes, int n_in,
                              void* d_out, int out_size) {
    const float* emb      = (const float*)d_in[0];
    const float* Ws0      = (const float*)d_in[1];
    const float* bs0      = (const float*)d_in[2];
    const float* Wn0      = (const float*)d_in[3];
    const float* bn0      = (const float*)d_in[4];
    const float* Ws1      = (const float*)d_in[5];
    const float* bs1      = (const float*)d_in[6];
    const float* Wn1      = (const float*)d_in[7];
    const float* bn1      = (const float*)d_in[8];
    const float* Wout     = (const float*)d_in[9];
    const float* bout     = (const float*)d_in[10];
    const int*   in_nodes = (const int*)d_in[11];
    const int*   nbr0     = (const int*)d_in[12];
    const int*   nbr1     = (const int*)d_in[13];
    float* out = (float*)d_out;

    cudaFuncSetAttribute(gemm0_tc_kernel,
                         cudaFuncAttributeMaxDynamicSharedMemorySize, GEMM0_SM_BYTES);

    // merged weight prep
    prep_all<<<192, 256>>>(Ws0, bs0, Wn0, bn0, Ws1, bs1, Wn1, bn1, Wout, bout);

    // layer 0: MLP-batched gather, then 3-stage tensor-core GEMM
    gather0_kernel<<<N_DST0 / 64, 256>>>(emb, in_nodes, nbr0);
    gemm0_tc_kernel<<<N_DST0 / 128, 256, GEMM0_SM_BYTES>>>();

    // layer 1 gather, then fused (layer1 + output-projection) GEMM
    gather1_kernel<<<(N_DST1 * 32) / 256, 256>>>(nbr1);
    gemm1_kernel<<<N_DST1 / 4, 256>>>(out);
}

// round 11
// speedup vs baseline: 1.0696x; 1.0696x over previous
#include <cuda_runtime.h>
#include <cuda_bf16.h>
#include <cstdint>

// Problem dims
#define NUM_NODES 1000000
#define HIDDEN    128
#define OUT_DIM   64
#define FANOUT    16
#define N_SRC0    1048576
#define N_DST0    65536
#define N_DST1    4096

#define G0_BLOCKS (N_DST0 / 64)          // 1024 gather CTAs
#define PREP_BLOCKS 192                  // 128 (W0) + 64 (Wf)

// ---------------- scratch (static device globals; no allocations) ----------
__device__ uint32_t g_X0[(size_t)N_DST0 * 256];   // tf32 BITS [self|mean]
__device__ float    g_H1[(size_t)N_DST0 * 128];   // layer-0 output (post-ReLU)
__device__ float    g_X1[(size_t)N_DST1 * 256];   // [self | mean] per dst1 row
__device__ uint32_t g_W0T[256 * 128];             // tf32 BITS: [k][n] = cat(Ws0,Wn0)^T
__device__ float    g_b0[128];                    // b_self0 + b_neigh0
__device__ float    g_WfT[256 * 64];              // [k][n] = (W_out @ cat(Ws1,Wn1))^T
__device__ float    g_bf[64];                     // W_out @ (bs1+bn1) + b_out

// ---------------- helpers --------------------------------------------------
__device__ __forceinline__ uint32_t f2tf32(float f) {
    uint32_t r; asm("cvt.rna.tf32.f32 %0, %1;" : "=r"(r) : "f"(f)); return r;
}

__device__ __forceinline__ float4 f4add(float4 a, float4 b) {
    return make_float4(a.x + b.x, a.y + b.y, a.z + b.z, a.w + b.w);
}

__device__ __forceinline__ uint32_t smem_u32(const void* p) {
    uint32_t a;
    asm("{ .reg .u64 t; cvta.to.shared.u64 t, %1; cvt.u32.u64 %0, t; }" : "=r"(a) : "l"(p));
    return a;
}

__device__ __forceinline__ void mma_tf32(float c[4],
                                         uint32_t a0, uint32_t a1, uint32_t a2, uint32_t a3,
                                         uint32_t b0, uint32_t b1) {
    asm volatile(
        "mma.sync.aligned.m16n8k8.row.col.f32.tf32.tf32.f32 "
        "{%0,%1,%2,%3}, {%4,%5,%6,%7}, {%8,%9}, {%0,%1,%2,%3};"
        : "+f"(c[0]), "+f"(c[1]), "+f"(c[2]), "+f"(c[3])
        : "r"(a0), "r"(a1), "r"(a2), "r"(a3), "r"(b0), "r"(b1));
}

// ---------------- gather0 + prep, one launch --------------------------------
// bid < G0_BLOCKS: register-batched gather (proven). bid >= G0_BLOCKS: weight
// prep, fully hidden under the gather wall. Same-stream ordering guarantees
// gemm0 sees completed weights.
__global__ __launch_bounds__(256, 4) void gather0_prep_kernel(
    const float* __restrict__ emb, const int* __restrict__ input_nodes,
    const int* __restrict__ nbr0,
    const float* __restrict__ Ws0, const float* __restrict__ bs0,
    const float* __restrict__ Wn0, const float* __restrict__ bn0,
    const float* __restrict__ Ws1, const float* __restrict__ bs1,
    const float* __restrict__ Wn1, const float* __restrict__ bn1,
    const float* __restrict__ Wout, const float* __restrict__ bout) {

    if (blockIdx.x >= G0_BLOCKS) {
        // ---------------- prep path ----------------
        const int pb = blockIdx.x - G0_BLOCKS;
        if (pb < 128) {
            int idx = pb * 256 + threadIdx.x;              // 0..32767
            int k = idx >> 7;
            int n = idx & 127;
            float v = (k < 128) ? Ws0[n * 128 + k] : Wn0[n * 128 + (k - 128)];
            g_W0T[idx] = f2tf32(v);
            if (idx < 128) g_b0[idx] = bs0[idx] + bn0[idx];
        } else {
            int idx = (pb - 128) * 256 + threadIdx.x;      // 0..16383
            int k = idx >> 6;
            int n = idx & 63;
            float acc = 0.f;
            if (k < 128) {
                #pragma unroll 4
                for (int r = 0; r < 128; r++) acc += Wout[n * 128 + r] * Ws1[r * 128 + k];
            } else {
                int kk = k - 128;
                #pragma unroll 4
                for (int r = 0; r < 128; r++) acc += Wout[n * 128 + r] * Wn1[r * 128 + kk];
            }
            g_WfT[k * 64 + n] = acc;
            if (idx < 64) {
                float a2 = bout[idx];
                #pragma unroll 4
                for (int r = 0; r < 128; r++) a2 += Wout[idx * 128 + r] * (bs1[r] + bn1[r]);
                g_bf[idx] = a2;
            }
        }
        return;
    }

    // ---------------- gather path (register-batched, proven) ----------------
    __shared__ int s_idx[64 * FANOUT];
    __shared__ int s_self[64];

    const int tid  = threadIdx.x;
    const int lane = tid & 31;
    const int wid  = tid >> 5;
    const int base = blockIdx.x * 64;

    #pragma unroll
    for (int it = 0; it < 4; it++) {
        int i = it * 256 + tid;
        s_idx[i] = input_nodes[nbr0[(size_t)base * FANOUT + i]];
    }
    if (tid < 64) s_self[tid] = input_nodes[base + tid];
    __syncthreads();

    const float4* E = (const float4*)emb;        // row stride = 32 float4
    const float inv = 1.0f / (float)FANOUT;

    #pragma unroll 2
    for (int rr = 0; rr < 8; rr++) {
        const int r = wid * 8 + rr;

        int gj[FANOUT];
        #pragma unroll
        for (int j = 0; j < FANOUT; j++) gj[j] = s_idx[r * FANOUT + j];
        const int gs = s_self[r];

        float4 v0 = __ldg(&E[(size_t)gs * 32 + lane]);
        float4 n0 = __ldg(&E[(size_t)gj[0] * 32 + lane]);
        float4 n1 = __ldg(&E[(size_t)gj[1] * 32 + lane]);
        float4 n2 = __ldg(&E[(size_t)gj[2] * 32 + lane]);
        float4 n3 = __ldg(&E[(size_t)gj[3] * 32 + lane]);
        float4 n4 = __ldg(&E[(size_t)gj[4] * 32 + lane]);
        float4 n5 = __ldg(&E[(size_t)gj[5] * 32 + lane]);
        float4 n6 = __ldg(&E[(size_t)gj[6] * 32 + lane]);
        float4 n7 = __ldg(&E[(size_t)gj[7] * 32 + lane]);
        float4 t0 = f4add(n0, n1), t1 = f4add(n2, n3);
        float4 t2 = f4add(n4, n5), t3 = f4add(n6, n7);
        float4 acc1 = f4add(f4add(t0, t1), f4add(t2, t3));

        float4 m0 = __ldg(&E[(size_t)gj[8]  * 32 + lane]);
        float4 m1 = __ldg(&E[(size_t)gj[9]  * 32 + lane]);
        float4 m2 = __ldg(&E[(size_t)gj[10] * 32 + lane]);
        float4 m3 = __ldg(&E[(size_t)gj[11] * 32 + lane]);
        float4 m4 = __ldg(&E[(size_t)gj[12] * 32 + lane]);
        float4 m5 = __ldg(&E[(size_t)gj[13] * 32 + lane]);
        float4 m6 = __ldg(&E[(size_t)gj[14] * 32 + lane]);
        float4 m7 = __ldg(&E[(size_t)gj[15] * 32 + lane]);
        float4 u0 = f4add(m0, m1), u1 = f4add(m2, m3);
        float4 u2 = f4add(m4, m5), u3 = f4add(m6, m7);
        float4 acc2 = f4add(f4add(u0, u1), f4add(u2, u3));

        float4 acc = f4add(acc1, acc2);

        uint4 ts, tn;
        ts.x = f2tf32(v0.x); ts.y = f2tf32(v0.y); ts.z = f2tf32(v0.z); ts.w = f2tf32(v0.w);
        tn.x = f2tf32(acc.x * inv); tn.y = f2tf32(acc.y * inv);
        tn.z = f2tf32(acc.z * inv); tn.w = f2tf32(acc.w * inv);
        size_t row = (size_t)base + r;
        *(uint4*)&g_X0[row * 256 + lane * 4]       = ts;
        *(uint4*)&g_X0[row * 256 + 128 + lane * 4] = tn;
    }
}

// ---------------- gemm0: tf32 MMA, 3-stage cp.async, 1 sync/iter -----------
// g_H1 = relu(X0 @ W0T + b0).  M=65536, N=128, K=256. 128x128 CTA tile,
// BK=32, 8 warps 2(m) x 4(n).
#define AS_W (128 * 36)
#define BS_W (32 * 132)
#define STG_W (AS_W + BS_W)                       // 8832 words per stage
#define GEMM0_SM_BYTES (3 * STG_W * 4)            // 105984

__global__ __launch_bounds__(256, 2) void gemm0_tc_kernel() {
    extern __shared__ uint32_t sm[];

    const int tid  = threadIdx.x;
    const int l    = tid & 31;
    const int lm   = l >> 2;
    const int lk   = l & 3;
    const int wid  = tid >> 5;
    const int wm   = wid >> 2;
    const int wn   = wid & 3;
    const size_t block_row = (size_t)blockIdx.x * 128;
    const uint32_t* __restrict__ A = g_X0 + block_row * 256;
    const uint32_t* __restrict__ B = g_W0T;

    auto stageA = [&](int s) -> uint32_t (*)[36] {
        return (uint32_t (*)[36])(sm + s * STG_W);
    };
    auto stageB = [&](int s) -> uint32_t (*)[132] {
        return (uint32_t (*)[132])(sm + s * STG_W + AS_W);
    };

    auto prefetch = [&](int chunk) {
        const int s = chunk % 3;
        const int k0 = chunk * 32;
        uint32_t (*As)[36] = stageA(s);
        uint32_t (*Bs)[132] = stageB(s);
        #pragma unroll
        for (int it = 0; it < 4; it++) {
            int idx = it * 256 + tid;
            int row = idx >> 3;
            int c4  = idx & 7;
            uint32_t d = smem_u32(&As[row][c4 * 4]);
            const uint32_t* src = A + (size_t)row * 256 + k0 + c4 * 4;
            asm volatile("cp.async.cg.shared.global [%0], [%1], 16;" :: "r"(d), "l"(src));
        }
        #pragma unroll
        for (int it = 0; it < 4; it++) {
            int idx = it * 256 + tid;
            int kk = idx >> 5;
            int n4 = idx & 31;
            uint32_t d = smem_u32(&Bs[kk][n4 * 4]);
            const uint32_t* src = B + (size_t)(k0 + kk) * 128 + n4 * 4;
            asm volatile("cp.async.cg.shared.global [%0], [%1], 16;" :: "r"(d), "l"(src));
        }
        asm volatile("cp.async.commit_group;" ::: "memory");
    };

    float acc[4][4][4];
    #pragma unroll
    for (int i = 0; i < 4; i++)
        #pragma unroll
        for (int j = 0; j < 4; j++)
            #pragma unroll
            for (int c = 0; c < 4; c++) acc[i][j][c] = 0.f;

    prefetch(0);
    prefetch(1);

    #pragma unroll
    for (int ch = 0; ch < 8; ch++) {
        const int s = ch % 3;
        if (ch < 7) {
            asm volatile("cp.async.wait_group 1;" ::: "memory");
        } else {
            asm volatile("cp.async.wait_group 0;" ::: "memory");
        }
        __syncthreads();
        if (ch + 2 < 8) prefetch(ch + 2);   // writes buffer (ch+2)%3 — free

        uint32_t (*As)[36] = stageA(s);
        uint32_t (*Bs)[132] = stageB(s);
        #pragma unroll
        for (int kk = 0; kk < 4; kk++) {
            const int k8 = kk * 8;
            uint32_t af[4][4], bf[4][2];
            #pragma unroll
            for (int mt = 0; mt < 4; mt++) {
                int mrow = wm * 64 + mt * 16 + lm;
                af[mt][0] = As[mrow    ][k8 + lk];
                af[mt][1] = As[mrow + 8][k8 + lk];
                af[mt][2] = As[mrow    ][k8 + lk + 4];
                af[mt][3] = As[mrow + 8][k8 + lk + 4];
            }
            #pragma unroll
            for (int nt = 0; nt < 4; nt++) {
                int ncol = wn * 32 + nt * 8 + lm;
                bf[nt][0] = Bs[k8 + lk    ][ncol];
                bf[nt][1] = Bs[k8 + lk + 4][ncol];
            }
            #pragma unroll
            for (int mt = 0; mt < 4; mt++)
                #pragma unroll
                for (int nt = 0; nt < 4; nt++)
                    mma_tf32(acc[mt][nt], af[mt][0], af[mt][1], af[mt][2], af[mt][3],
                             bf[nt][0], bf[nt][1]);
        }
    }

    float2* __restrict__ H2 = (float2*)g_H1;      // row stride = 64 float2
    #pragma unroll
    for (int nt = 0; nt < 4; nt++) {
        int col = wn * 32 + nt * 8 + lk * 2;
        float bv0 = g_b0[col], bv1 = g_b0[col + 1];
        #pragma unroll
        for (int mt = 0; mt < 4; mt++) {
            size_t row0 = block_row + wm * 64 + mt * 16 + lm;
            float2 v0 = make_float2(fmaxf(acc[mt][nt][0] + bv0, 0.f),
                                    fmaxf(acc[mt][nt][1] + bv1, 0.f));
            float2 v1 = make_float2(fmaxf(acc[mt][nt][2] + bv0, 0.f),
                                    fmaxf(acc[mt][nt][3] + bv1, 0.f));
            H2[row0 * 64 + (col >> 1)]       = v0;
            H2[(row0 + 8) * 64 + (col >> 1)] = v1;
        }
    }
}

// ---------------- layer-1 gather: register-batched (L2-hot H1) -------------
__global__ __launch_bounds__(256) void gather1_kernel(const int* __restrict__ nbr1) {
    int warp = (blockIdx.x * blockDim.x + threadIdx.x) >> 5;
    int lane = threadIdx.x & 31;
    if (warp >= N_DST1) return;

    int nj = 0;
    if (lane < FANOUT) nj = nbr1[warp * FANOUT + lane];

    int gj[FANOUT];
    #pragma unroll
    for (int j = 0; j < FANOUT; j++) gj[j] = __shfl_sync(0xffffffffu, nj, j);

    const float4* H = (const float4*)g_H1;                // row stride = 32 float4
    float4 s  = __ldg(&H[(size_t)warp * 32 + lane]);
    float4 n0 = __ldg(&H[(size_t)gj[0] * 32 + lane]);
    float4 n1 = __ldg(&H[(size_t)gj[1] * 32 + lane]);
    float4 n2 = __ldg(&H[(size_t)gj[2] * 32 + lane]);
    float4 n3 = __ldg(&H[(size_t)gj[3] * 32 + lane]);
    float4 n4 = __ldg(&H[(size_t)gj[4] * 32 + lane]);
    float4 n5 = __ldg(&H[(size_t)gj[5] * 32 + lane]);
    float4 n6 = __ldg(&H[(size_t)gj[6] * 32 + lane]);
    float4 n7 = __ldg(&H[(size_t)gj[7] * 32 + lane]);
    float4 t0 = f4add(n0, n1), t1 = f4add(n2, n3);
    float4 t2 = f4add(n4, n5), t3 = f4add(n6, n7);
    float4 acc1 = f4add(f4add(t0, t1), f4add(t2, t3));

    float4 m0 = __ldg(&H[(size_t)gj[8]  * 32 + lane]);
    float4 m1 = __ldg(&H[(size_t)gj[9]  * 32 + lane]);
    float4 m2 = __ldg(&H[(size_t)gj[10] * 32 + lane]);
    float4 m3 = __ldg(&H[(size_t)gj[11] * 32 + lane]);
    float4 m4 = __ldg(&H[(size_t)gj[12] * 32 + lane]);
    float4 m5 = __ldg(&H[(size_t)gj[13] * 32 + lane]);
    float4 m6 = __ldg(&H[(size_t)gj[14] * 32 + lane]);
    float4 m7 = __ldg(&H[(size_t)gj[15] * 32 + lane]);
    float4 u0 = f4add(m0, m1), u1 = f4add(m2, m3);
    float4 u2 = f4add(m4, m5), u3 = f4add(m6, m7);
    float4 acc2 = f4add(f4add(u0, u1), f4add(u2, u3));

    float4 acc = f4add(acc1, acc2);
    const float inv = 1.0f / (float)FANOUT;

    float4* X = (float4*)g_X1;
    X[(size_t)warp * 64 + lane]      = s;
    X[(size_t)warp * 64 + 32 + lane] =
        make_float4(acc.x * inv, acc.y * inv, acc.z * inv, acc.w * inv);
}

// ---------------- gemm1: out = g_X1 @ g_WfT + g_bf -------------------------
__global__ __launch_bounds__(256) void gemm1_kernel(float* __restrict__ C) {
    __shared__ float Bs[64][65];
    int tid = threadIdx.x;
    int r = blockIdx.x * 4 + (tid >> 6);
    int n = tid & 63;
    float acc = g_bf[n];
    for (int k0 = 0; k0 < 256; k0 += 64) {
        for (int i = tid; i < 64 * 64; i += 256)
            Bs[i >> 6][i & 63] = g_WfT[(size_t)(k0 + (i >> 6)) * 64 + (i & 63)];
        __syncthreads();
        const float* Ar = g_X1 + (size_t)r * 256 + k0;
        #pragma unroll 16
        for (int k = 0; k < 64; k++) acc = fmaf(Ar[k], Bs[k][n], acc);
        __syncthreads();
    }
    C[(size_t)r * 64 + n] = acc;
}

// ---------------- launch ---------------------------------------------------
extern "C" void kernel_launch(void* const* d_in, const int* in_sizes, int n_in,
                              void* d_out, int out_size) {
    const float* emb      = (const float*)d_in[0];
    const float* Ws0      = (const float*)d_in[1];
    const float* bs0      = (const float*)d_in[2];
    const float* Wn0      = (const float*)d_in[3];
    const float* bn0      = (const float*)d_in[4];
    const float* Ws1      = (const float*)d_in[5];
    const float* bs1      = (const float*)d_in[6];
    const float* Wn1      = (const float*)d_in[7];
    const float* bn1      = (const float*)d_in[8];
    const float* Wout     = (const float*)d_in[9];
    const float* bout     = (const float*)d_in[10];
    const int*   in_nodes = (const int*)d_in[11];
    const int*   nbr0     = (const int*)d_in[12];
    const int*   nbr1     = (const int*)d_in[13];
    float* out = (float*)d_out;

    cudaFuncSetAttribute(gemm0_tc_kernel,
                         cudaFuncAttributeMaxDynamicSharedMemorySize, GEMM0_SM_BYTES);

    // layer 0: gather + weight prep in ONE launch (prep hides under gather),
    // then 3-stage tensor-core GEMM
    gather0_prep_kernel<<<G0_BLOCKS + PREP_BLOCKS, 256>>>(
        emb, in_nodes, nbr0,
        Ws0, bs0, Wn0, bn0, Ws1, bs1, Wn1, bn1, Wout, bout);
    gemm0_tc_kernel<<<N_DST0 / 128, 256, GEMM0_SM_BYTES>>>();

    // layer 1 gather (register-batched), then fused output GEMM
    gather1_kernel<<<(N_DST1 * 32) / 256, 256>>>(nbr1);
    gemm1_kernel<<<N_DST1 / 4, 256>>>(out);
}

// round 12
// speedup vs baseline: 1.1749x; 1.0985x over previous
#include <cuda_runtime.h>
#include <cuda_bf16.h>
#include <cstdint>

// Problem dims
#define NUM_NODES 1000000
#define HIDDEN    128
#define OUT_DIM   64
#define FANOUT    16
#define N_SRC0    1048576
#define N_DST0    65536
#define N_DST1    4096

#define G0_BLOCKS (N_DST0 / 64)          // 1024 gather CTAs
#define PREP_BLOCKS 192                  // 128 (W0) + 64 (Wf)

// ---------------- scratch (static device globals; no allocations) ----------
__device__ uint32_t g_X0[(size_t)N_DST0 * 256];   // tf32 BITS [self|mean]
__device__ float    g_H1[(size_t)N_DST0 * 128];   // layer-0 output (post-ReLU)
__device__ uint32_t g_X1[(size_t)N_DST1 * 256];   // tf32 BITS [self|mean] dst1
__device__ uint32_t g_W0T[256 * 128];             // tf32 BITS: [k][n] = cat(Ws0,Wn0)^T
__device__ float    g_b0[128];                    // b_self0 + b_neigh0
__device__ uint32_t g_WfT[256 * 64];              // tf32 BITS: [k][n] = (W_out @ cat(Ws1,Wn1))^T
__device__ float    g_bf[64];                     // W_out @ (bs1+bn1) + b_out

// ---------------- helpers --------------------------------------------------
__device__ __forceinline__ uint32_t f2tf32(float f) {
    uint32_t r; asm("cvt.rna.tf32.f32 %0, %1;" : "=r"(r) : "f"(f)); return r;
}

__device__ __forceinline__ float4 f4add(float4 a, float4 b) {
    return make_float4(a.x + b.x, a.y + b.y, a.z + b.z, a.w + b.w);
}

__device__ __forceinline__ uint32_t smem_u32(const void* p) {
    uint32_t a;
    asm("{ .reg .u64 t; cvta.to.shared.u64 t, %1; cvt.u32.u64 %0, t; }" : "=r"(a) : "l"(p));
    return a;
}

__device__ __forceinline__ void mma_tf32(float c[4],
                                         uint32_t a0, uint32_t a1, uint32_t a2, uint32_t a3,
                                         uint32_t b0, uint32_t b1) {
    asm volatile(
        "mma.sync.aligned.m16n8k8.row.col.f32.tf32.tf32.f32 "
        "{%0,%1,%2,%3}, {%4,%5,%6,%7}, {%8,%9}, {%0,%1,%2,%3};"
        : "+f"(c[0]), "+f"(c[1]), "+f"(c[2]), "+f"(c[3])
        : "r"(a0), "r"(a1), "r"(a2), "r"(a3), "r"(b0), "r"(b1));
}

// ---------------- gather0 + prep, one launch --------------------------------
__global__ __launch_bounds__(256, 4) void gather0_prep_kernel(
    const float* __restrict__ emb, const int* __restrict__ input_nodes,
    const int* __restrict__ nbr0,
    const float* __restrict__ Ws0, const float* __restrict__ bs0,
    const float* __restrict__ Wn0, const float* __restrict__ bn0,
    const float* __restrict__ Ws1, const float* __restrict__ bs1,
    const float* __restrict__ Wn1, const float* __restrict__ bn1,
    const float* __restrict__ Wout, const float* __restrict__ bout) {

    if (blockIdx.x >= G0_BLOCKS) {
        // ---------------- prep path ----------------
        const int pb = blockIdx.x - G0_BLOCKS;
        if (pb < 128) {
            int idx = pb * 256 + threadIdx.x;              // 0..32767
            int k = idx >> 7;
            int n = idx & 127;
            float v = (k < 128) ? Ws0[n * 128 + k] : Wn0[n * 128 + (k - 128)];
            g_W0T[idx] = f2tf32(v);
            if (idx < 128) g_b0[idx] = bs0[idx] + bn0[idx];
        } else {
            int idx = (pb - 128) * 256 + threadIdx.x;      // 0..16383
            int k = idx >> 6;
            int n = idx & 63;
            float acc = 0.f;
            if (k < 128) {
                #pragma unroll 4
                for (int r = 0; r < 128; r++) acc += Wout[n * 128 + r] * Ws1[r * 128 + k];
            } else {
                int kk = k - 128;
                #pragma unroll 4
                for (int r = 0; r < 128; r++) acc += Wout[n * 128 + r] * Wn1[r * 128 + kk];
            }
            g_WfT[k * 64 + n] = f2tf32(acc);
            if (idx < 64) {
                float a2 = bout[idx];
                #pragma unroll 4
                for (int r = 0; r < 128; r++) a2 += Wout[idx * 128 + r] * (bs1[r] + bn1[r]);
                g_bf[idx] = a2;
            }
        }
        return;
    }

    // ---------------- gather path (register-batched, proven) ----------------
    __shared__ int s_idx[64 * FANOUT];
    __shared__ int s_self[64];

    const int tid  = threadIdx.x;
    const int lane = tid & 31;
    const int wid  = tid >> 5;
    const int base = blockIdx.x * 64;

    #pragma unroll
    for (int it = 0; it < 4; it++) {
        int i = it * 256 + tid;
        s_idx[i] = input_nodes[nbr0[(size_t)base * FANOUT + i]];
    }
    if (tid < 64) s_self[tid] = input_nodes[base + tid];
    __syncthreads();

    const float4* E = (const float4*)emb;        // row stride = 32 float4
    const float inv = 1.0f / (float)FANOUT;

    #pragma unroll 2
    for (int rr = 0; rr < 8; rr++) {
        const int r = wid * 8 + rr;

        int gj[FANOUT];
        #pragma unroll
        for (int j = 0; j < FANOUT; j++) gj[j] = s_idx[r * FANOUT + j];
        const int gs = s_self[r];

        float4 v0 = __ldg(&E[(size_t)gs * 32 + lane]);
        float4 n0 = __ldg(&E[(size_t)gj[0] * 32 + lane]);
        float4 n1 = __ldg(&E[(size_t)gj[1] * 32 + lane]);
        float4 n2 = __ldg(&E[(size_t)gj[2] * 32 + lane]);
        float4 n3 = __ldg(&E[(size_t)gj[3] * 32 + lane]);
        float4 n4 = __ldg(&E[(size_t)gj[4] * 32 + lane]);
        float4 n5 = __ldg(&E[(size_t)gj[5] * 32 + lane]);
        float4 n6 = __ldg(&E[(size_t)gj[6] * 32 + lane]);
        float4 n7 = __ldg(&E[(size_t)gj[7] * 32 + lane]);
        float4 t0 = f4add(n0, n1), t1 = f4add(n2, n3);
        float4 t2 = f4add(n4, n5), t3 = f4add(n6, n7);
        float4 acc1 = f4add(f4add(t0, t1), f4add(t2, t3));

        float4 m0 = __ldg(&E[(size_t)gj[8]  * 32 + lane]);
        float4 m1 = __ldg(&E[(size_t)gj[9]  * 32 + lane]);
        float4 m2 = __ldg(&E[(size_t)gj[10] * 32 + lane]);
        float4 m3 = __ldg(&E[(size_t)gj[11] * 32 + lane]);
        float4 m4 = __ldg(&E[(size_t)gj[12] * 32 + lane]);
        float4 m5 = __ldg(&E[(size_t)gj[13] * 32 + lane]);
        float4 m6 = __ldg(&E[(size_t)gj[14] * 32 + lane]);
        float4 m7 = __ldg(&E[(size_t)gj[15] * 32 + lane]);
        float4 u0 = f4add(m0, m1), u1 = f4add(m2, m3);
        float4 u2 = f4add(m4, m5), u3 = f4add(m6, m7);
        float4 acc2 = f4add(f4add(u0, u1), f4add(u2, u3));

        float4 acc = f4add(acc1, acc2);

        uint4 ts, tn;
        ts.x = f2tf32(v0.x); ts.y = f2tf32(v0.y); ts.z = f2tf32(v0.z); ts.w = f2tf32(v0.w);
        tn.x = f2tf32(acc.x * inv); tn.y = f2tf32(acc.y * inv);
        tn.z = f2tf32(acc.z * inv); tn.w = f2tf32(acc.w * inv);
        size_t row = (size_t)base + r;
        *(uint4*)&g_X0[row * 256 + lane * 4]       = ts;
        *(uint4*)&g_X0[row * 256 + 128 + lane * 4] = tn;
    }
}

// ---------------- gemm0: tf32 MMA, 3-stage cp.async, 1 sync/iter -----------
#define AS_W (128 * 36)
#define BS_W (32 * 132)
#define STG_W (AS_W + BS_W)                       // 8832 words per stage
#define GEMM0_SM_BYTES (3 * STG_W * 4)            // 105984

__global__ __launch_bounds__(256, 2) void gemm0_tc_kernel() {
    extern __shared__ uint32_t sm[];

    const int tid  = threadIdx.x;
    const int l    = tid & 31;
    const int lm   = l >> 2;
    const int lk   = l & 3;
    const int wid  = tid >> 5;
    const int wm   = wid >> 2;
    const int wn   = wid & 3;
    const size_t block_row = (size_t)blockIdx.x * 128;
    const uint32_t* __restrict__ A = g_X0 + block_row * 256;
    const uint32_t* __restrict__ B = g_W0T;

    auto stageA = [&](int s) -> uint32_t (*)[36] {
        return (uint32_t (*)[36])(sm + s * STG_W);
    };
    auto stageB = [&](int s) -> uint32_t (*)[132] {
        return (uint32_t (*)[132])(sm + s * STG_W + AS_W);
    };

    auto prefetch = [&](int chunk) {
        const int s = chunk % 3;
        const int k0 = chunk * 32;
        uint32_t (*As)[36] = stageA(s);
        uint32_t (*Bs)[132] = stageB(s);
        #pragma unroll
        for (int it = 0; it < 4; it++) {
            int idx = it * 256 + tid;
            int row = idx >> 3;
            int c4  = idx & 7;
            uint32_t d = smem_u32(&As[row][c4 * 4]);
            const uint32_t* src = A + (size_t)row * 256 + k0 + c4 * 4;
            asm volatile("cp.async.cg.shared.global [%0], [%1], 16;" :: "r"(d), "l"(src));
        }
        #pragma unroll
        for (int it = 0; it < 4; it++) {
            int idx = it * 256 + tid;
            int kk = idx >> 5;
            int n4 = idx & 31;
            uint32_t d = smem_u32(&Bs[kk][n4 * 4]);
            const uint32_t* src = B + (size_t)(k0 + kk) * 128 + n4 * 4;
            asm volatile("cp.async.cg.shared.global [%0], [%1], 16;" :: "r"(d), "l"(src));
        }
        asm volatile("cp.async.commit_group;" ::: "memory");
    };

    float acc[4][4][4];
    #pragma unroll
    for (int i = 0; i < 4; i++)
        #pragma unroll
        for (int j = 0; j < 4; j++)
            #pragma unroll
            for (int c = 0; c < 4; c++) acc[i][j][c] = 0.f;

    prefetch(0);
    prefetch(1);

    #pragma unroll
    for (int ch = 0; ch < 8; ch++) {
        const int s = ch % 3;
        if (ch < 7) {
            asm volatile("cp.async.wait_group 1;" ::: "memory");
        } else {
            asm volatile("cp.async.wait_group 0;" ::: "memory");
        }
        __syncthreads();
        if (ch + 2 < 8) prefetch(ch + 2);   // writes buffer (ch+2)%3 — free

        uint32_t (*As)[36] = stageA(s);
        uint32_t (*Bs)[132] = stageB(s);
        #pragma unroll
        for (int kk = 0; kk < 4; kk++) {
            const int k8 = kk * 8;
            uint32_t af[4][4], bf[4][2];
            #pragma unroll
            for (int mt = 0; mt < 4; mt++) {
                int mrow = wm * 64 + mt * 16 + lm;
                af[mt][0] = As[mrow    ][k8 + lk];
                af[mt][1] = As[mrow + 8][k8 + lk];
                af[mt][2] = As[mrow    ][k8 + lk + 4];
                af[mt][3] = As[mrow + 8][k8 + lk + 4];
            }
            #pragma unroll
            for (int nt = 0; nt < 4; nt++) {
                int ncol = wn * 32 + nt * 8 + lm;
                bf[nt][0] = Bs[k8 + lk    ][ncol];
                bf[nt][1] = Bs[k8 + lk + 4][ncol];
            }
            #pragma unroll
            for (int mt = 0; mt < 4; mt++)
                #pragma unroll
                for (int nt = 0; nt < 4; nt++)
                    mma_tf32(acc[mt][nt], af[mt][0], af[mt][1], af[mt][2], af[mt][3],
                             bf[nt][0], bf[nt][1]);
        }
    }

    float2* __restrict__ H2 = (float2*)g_H1;      // row stride = 64 float2
    #pragma unroll
    for (int nt = 0; nt < 4; nt++) {
        int col = wn * 32 + nt * 8 + lk * 2;
        float bv0 = g_b0[col], bv1 = g_b0[col + 1];
        #pragma unroll
        for (int mt = 0; mt < 4; mt++) {
            size_t row0 = block_row + wm * 64 + mt * 16 + lm;
            float2 v0 = make_float2(fmaxf(acc[mt][nt][0] + bv0, 0.f),
                                    fmaxf(acc[mt][nt][1] + bv1, 0.f));
            float2 v1 = make_float2(fmaxf(acc[mt][nt][2] + bv0, 0.f),
                                    fmaxf(acc[mt][nt][3] + bv1, 0.f));
            H2[row0 * 64 + (col >> 1)]       = v0;
            H2[(row0 + 8) * 64 + (col >> 1)] = v1;
        }
    }
}

// ---------------- layer-1 gather: register-batched, writes tf32 X1 ---------
__global__ __launch_bounds__(256) void gather1_kernel(const int* __restrict__ nbr1) {
    int warp = (blockIdx.x * blockDim.x + threadIdx.x) >> 5;
    int lane = threadIdx.x & 31;
    if (warp >= N_DST1) return;

    int nj = 0;
    if (lane < FANOUT) nj = nbr1[warp * FANOUT + lane];

    int gj[FANOUT];
    #pragma unroll
    for (int j = 0; j < FANOUT; j++) gj[j] = __shfl_sync(0xffffffffu, nj, j);

    const float4* H = (const float4*)g_H1;                // row stride = 32 float4
    float4 s  = __ldg(&H[(size_t)warp * 32 + lane]);
    float4 n0 = __ldg(&H[(size_t)gj[0] * 32 + lane]);
    float4 n1 = __ldg(&H[(size_t)gj[1] * 32 + lane]);
    float4 n2 = __ldg(&H[(size_t)gj[2] * 32 + lane]);
    float4 n3 = __ldg(&H[(size_t)gj[3] * 32 + lane]);
    float4 n4 = __ldg(&H[(size_t)gj[4] * 32 + lane]);
    float4 n5 = __ldg(&H[(size_t)gj[5] * 32 + lane]);
    float4 n6 = __ldg(&H[(size_t)gj[6] * 32 + lane]);
    float4 n7 = __ldg(&H[(size_t)gj[7] * 32 + lane]);
    float4 t0 = f4add(n0, n1), t1 = f4add(n2, n3);
    float4 t2 = f4add(n4, n5), t3 = f4add(n6, n7);
    float4 acc1 = f4add(f4add(t0, t1), f4add(t2, t3));

    float4 m0 = __ldg(&H[(size_t)gj[8]  * 32 + lane]);
    float4 m1 = __ldg(&H[(size_t)gj[9]  * 32 + lane]);
    float4 m2 = __ldg(&H[(size_t)gj[10] * 32 + lane]);
    float4 m3 = __ldg(&H[(size_t)gj[11] * 32 + lane]);
    float4 m4 = __ldg(&H[(size_t)gj[12] * 32 + lane]);
    float4 m5 = __ldg(&H[(size_t)gj[13] * 32 + lane]);
    float4 m6 = __ldg(&H[(size_t)gj[14] * 32 + lane]);
    float4 m7 = __ldg(&H[(size_t)gj[15] * 32 + lane]);
    float4 u0 = f4add(m0, m1), u1 = f4add(m2, m3);
    float4 u2 = f4add(m4, m5), u3 = f4add(m6, m7);
    float4 acc2 = f4add(f4add(u0, u1), f4add(u2, u3));

    float4 acc = f4add(acc1, acc2);
    const float inv = 1.0f / (float)FANOUT;

    uint4 ts, tn;
    ts.x = f2tf32(s.x); ts.y = f2tf32(s.y); ts.z = f2tf32(s.z); ts.w = f2tf32(s.w);
    tn.x = f2tf32(acc.x * inv); tn.y = f2tf32(acc.y * inv);
    tn.z = f2tf32(acc.z * inv); tn.w = f2tf32(acc.w * inv);
    *(uint4*)&g_X1[(size_t)warp * 256 + lane * 4]       = ts;
    *(uint4*)&g_X1[(size_t)warp * 256 + 128 + lane * 4] = tn;
}

// ---------------- gemm1 (tensor cores): out = X1 @ WfT + bf ----------------
// M=4096, N=64, K=256. CTA tile 64x64, 8 warps 2(m) x 4(n), warp tile 32x16.
__global__ __launch_bounds__(256) void gemm1_tc_kernel(float* __restrict__ C) {
    __shared__ uint32_t As[64][36];
    __shared__ uint32_t Bs[32][68];

    const int tid  = threadIdx.x;
    const int l    = tid & 31;
    const int lm   = l >> 2;
    const int lk   = l & 3;
    const int wid  = tid >> 5;
    const int wm   = wid >> 2;          // 0..1 -> rows wm*32..
    const int wn   = wid & 3;           // 0..3 -> cols wn*16..
    const size_t block_row = (size_t)blockIdx.x * 64;
    const uint32_t* __restrict__ A = g_X1 + block_row * 256;
    const uint32_t* __restrict__ B = g_WfT;

    float acc[2][2][4];
    #pragma unroll
    for (int i = 0; i < 2; i++)
        #pragma unroll
        for (int j = 0; j < 2; j++)
            #pragma unroll
            for (int c = 0; c < 4; c++) acc[i][j][c] = 0.f;

    for (int k0 = 0; k0 < 256; k0 += 32) {
        // A tile: 64 rows x 32 k = 512 uint4 -> 2 iters
        #pragma unroll
        for (int it = 0; it < 2; it++) {
            int idx = it * 256 + tid;
            int row = idx >> 3;
            int c4  = idx & 7;
            *(uint4*)&As[row][c4 * 4] =
                *(const uint4*)(A + (size_t)row * 256 + k0 + c4 * 4);
        }
        // B tile: 32 k x 64 n = 512 uint4 -> 2 iters
        #pragma unroll
        for (int it = 0; it < 2; it++) {
            int idx = it * 256 + tid;
            int kk = idx >> 4;
            int n4 = idx & 15;
            *(uint4*)&Bs[kk][n4 * 4] =
                *(const uint4*)(B + (size_t)(k0 + kk) * 64 + n4 * 4);
        }
        __syncthreads();

        #pragma unroll
        for (int kk = 0; kk < 4; kk++) {
            const int k8 = kk * 8;
            uint32_t af[2][4], bf[2][2];
            #pragma unroll
            for (int mt = 0; mt < 2; mt++) {
                int mrow = wm * 32 + mt * 16 + lm;
                af[mt][0] = As[mrow    ][k8 + lk];
                af[mt][1] = As[mrow + 8][k8 + lk];
                af[mt][2] = As[mrow    ][k8 + lk + 4];
                af[mt][3] = As[mrow + 8][k8 + lk + 4];
            }
            #pragma unroll
            for (int nt = 0; nt < 2; nt++) {
                int ncol = wn * 16 + nt * 8 + lm;
                bf[nt][0] = Bs[k8 + lk    ][ncol];
                bf[nt][1] = Bs[k8 + lk + 4][ncol];
            }
            #pragma unroll
            for (int mt = 0; mt < 2; mt++)
                #pragma unroll
                for (int nt = 0; nt < 2; nt++)
                    mma_tf32(acc[mt][nt], af[mt][0], af[mt][1], af[mt][2], af[mt][3],
                             bf[nt][0], bf[nt][1]);
        }
        __syncthreads();
    }

    // epilogue: +bf, write float2
    #pragma unroll
    for (int nt = 0; nt < 2; nt++) {
        int col = wn * 16 + nt * 8 + lk * 2;
        float bv0 = g_bf[col], bv1 = g_bf[col + 1];
        #pragma unroll
        for (int mt = 0; mt < 2; mt++) {
            size_t row0 = block_row + wm * 32 + mt * 16 + lm;
            float2* c0 = (float2*)(C + row0 * 64 + col);
            float2* c1 = (float2*)(C + (row0 + 8) * 64 + col);
            *c0 = make_float2(acc[mt][nt][0] + bv0, acc[mt][nt][1] + bv1);
            *c1 = make_float2(acc[mt][nt][2] + bv0, acc[mt][nt][3] + bv1);
        }
    }
}

// ---------------- launch ---------------------------------------------------
extern "C" void kernel_launch(void* const* d_in, const int* in_sizes, int n_in,
                              void* d_out, int out_size) {
    const float* emb      = (const float*)d_in[0];
    const float* Ws0      = (const float*)d_in[1];
    const float* bs0      = (const float*)d_in[2];
    const float* Wn0      = (const float*)d_in[3];
    const float* bn0      = (const float*)d_in[4];
    const float* Ws1      = (const float*)d_in[5];
    const float* bs1      = (const float*)d_in[6];
    const float* Wn1      = (const float*)d_in[7];
    const float* bn1      = (const float*)d_in[8];
    const float* Wout     = (const float*)d_in[9];
    const float* bout     = (const float*)d_in[10];
    const int*   in_nodes = (const int*)d_in[11];
    const int*   nbr0     = (const int*)d_in[12];
    const int*   nbr1     = (const int*)d_in[13];
    float* out = (float*)d_out;

    cudaFuncSetAttribute(gemm0_tc_kernel,
                         cudaFuncAttributeMaxDynamicSharedMemorySize, GEMM0_SM_BYTES);

    // layer 0: gather + weight prep in ONE launch, then 3-stage tc GEMM
    gather0_prep_kernel<<<G0_BLOCKS + PREP_BLOCKS, 256>>>(
        emb, in_nodes, nbr0,
        Ws0, bs0, Wn0, bn0, Ws1, bs1, Wn1, bn1, Wout, bout);
    gemm0_tc_kernel<<<N_DST0 / 128, 256, GEMM0_SM_BYTES>>>();

    // layer 1 gather (tf32 out), then tensor-core output GEMM
    gather1_kernel<<<(N_DST1 * 32) / 256, 256>>>(nbr1);
    gemm1_tc_kernel<<<N_DST1 / 64, 256>>>(out);
}

// round 13
// speedup vs baseline: 1.2017x; 1.0228x over previous
#include <cuda_runtime.h>
#include <cuda_bf16.h>
#include <cstdint>

// Problem dims
#define NUM_NODES 1000000
#define HIDDEN    128
#define OUT_DIM   64
#define FANOUT    16
#define N_SRC0    1048576
#define N_DST0    65536
#define N_DST1    4096

#define G0_BLOCKS (N_DST0 / 64)          // 1024 gather CTAs
#define PREP_BLOCKS 192                  // 128 (W0) + 64 (Wf)

// ---------------- scratch (static device globals; no allocations) ----------
__device__ uint32_t g_X0[(size_t)N_DST0 * 256];   // tf32 BITS [self|mean]
__device__ float    g_H1[(size_t)N_DST0 * 128];   // layer-0 output (post-ReLU)
__device__ uint32_t g_X1[(size_t)N_DST1 * 256];   // tf32 BITS [self|mean] dst1
__device__ uint32_t g_W0T[256 * 128];             // tf32 BITS: [k][n] = cat(Ws0,Wn0)^T
__device__ float    g_b0[128];                    // b_self0 + b_neigh0
__device__ uint32_t g_WfT[256 * 64];              // tf32 BITS: (W_out @ cat(Ws1,Wn1))^T
__device__ float    g_bf[64];                     // W_out @ (bs1+bn1) + b_out

// ---------------- helpers --------------------------------------------------
__device__ __forceinline__ uint32_t f2tf32(float f) {
    uint32_t r; asm("cvt.rna.tf32.f32 %0, %1;" : "=r"(r) : "f"(f)); return r;
}

__device__ __forceinline__ float4 f4add(float4 a, float4 b) {
    return make_float4(a.x + b.x, a.y + b.y, a.z + b.z, a.w + b.w);
}

__device__ __forceinline__ uint32_t smem_u32(const void* p) {
    uint32_t a;
    asm("{ .reg .u64 t; cvta.to.shared.u64 t, %1; cvt.u32.u64 %0, t; }" : "=r"(a) : "l"(p));
    return a;
}

__device__ __forceinline__ void mma_tf32(float c[4],
                                         uint32_t a0, uint32_t a1, uint32_t a2, uint32_t a3,
                                         uint32_t b0, uint32_t b1) {
    asm volatile(
        "mma.sync.aligned.m16n8k8.row.col.f32.tf32.tf32.f32 "
        "{%0,%1,%2,%3}, {%4,%5,%6,%7}, {%8,%9}, {%0,%1,%2,%3};"
        : "+f"(c[0]), "+f"(c[1]), "+f"(c[2]), "+f"(c[3])
        : "r"(a0), "r"(a1), "r"(a2), "r"(a3), "r"(b0), "r"(b1));
}

// ---------------- gather0 + prep, one launch --------------------------------
__global__ __launch_bounds__(256, 4) void gather0_prep_kernel(
    const float* __restrict__ emb, const int* __restrict__ input_nodes,
    const int* __restrict__ nbr0,
    const float* __restrict__ Ws0, const float* __restrict__ bs0,
    const float* __restrict__ Wn0, const float* __restrict__ bn0,
    const float* __restrict__ Ws1, const float* __restrict__ bs1,
    const float* __restrict__ Wn1, const float* __restrict__ bn1,
    const float* __restrict__ Wout, const float* __restrict__ bout) {

    if (blockIdx.x >= G0_BLOCKS) {
        // ---------------- prep path ----------------
        const int pb = blockIdx.x - G0_BLOCKS;
        if (pb < 128) {
            int idx = pb * 256 + threadIdx.x;              // 0..32767
            int k = idx >> 7;
            int n = idx & 127;
            float v = (k < 128) ? Ws0[n * 128 + k] : Wn0[n * 128 + (k - 128)];
            g_W0T[idx] = f2tf32(v);
            if (idx < 128) g_b0[idx] = bs0[idx] + bn0[idx];
        } else {
            int idx = (pb - 128) * 256 + threadIdx.x;      // 0..16383
            int k = idx >> 6;
            int n = idx & 63;
            float acc = 0.f;
            if (k < 128) {
                #pragma unroll 4
                for (int r = 0; r < 128; r++) acc += Wout[n * 128 + r] * Ws1[r * 128 + k];
            } else {
                int kk = k - 128;
                #pragma unroll 4
                for (int r = 0; r < 128; r++) acc += Wout[n * 128 + r] * Wn1[r * 128 + kk];
            }
            g_WfT[k * 64 + n] = f2tf32(acc);
            if (idx < 64) {
                float a2 = bout[idx];
                #pragma unroll 4
                for (int r = 0; r < 128; r++) a2 += Wout[idx * 128 + r] * (bs1[r] + bn1[r]);
                g_bf[idx] = a2;
            }
        }
        return;
    }

    // ---------------- gather path (register-batched, proven) ----------------
    __shared__ int s_idx[64 * FANOUT];
    __shared__ int s_self[64];

    const int tid  = threadIdx.x;
    const int lane = tid & 31;
    const int wid  = tid >> 5;
    const int base = blockIdx.x * 64;

    #pragma unroll
    for (int it = 0; it < 4; it++) {
        int i = it * 256 + tid;
        s_idx[i] = input_nodes[nbr0[(size_t)base * FANOUT + i]];
    }
    if (tid < 64) s_self[tid] = input_nodes[base + tid];
    __syncthreads();

    const float4* E = (const float4*)emb;        // row stride = 32 float4
    const float inv = 1.0f / (float)FANOUT;

    #pragma unroll 2
    for (int rr = 0; rr < 8; rr++) {
        const int r = wid * 8 + rr;

        int gj[FANOUT];
        #pragma unroll
        for (int j = 0; j < FANOUT; j++) gj[j] = s_idx[r * FANOUT + j];
        const int gs = s_self[r];

        float4 v0 = __ldg(&E[(size_t)gs * 32 + lane]);
        float4 n0 = __ldg(&E[(size_t)gj[0] * 32 + lane]);
        float4 n1 = __ldg(&E[(size_t)gj[1] * 32 + lane]);
        float4 n2 = __ldg(&E[(size_t)gj[2] * 32 + lane]);
        float4 n3 = __ldg(&E[(size_t)gj[3] * 32 + lane]);
        float4 n4 = __ldg(&E[(size_t)gj[4] * 32 + lane]);
        float4 n5 = __ldg(&E[(size_t)gj[5] * 32 + lane]);
        float4 n6 = __ldg(&E[(size_t)gj[6] * 32 + lane]);
        float4 n7 = __ldg(&E[(size_t)gj[7] * 32 + lane]);
        float4 t0 = f4add(n0, n1), t1 = f4add(n2, n3);
        float4 t2 = f4add(n4, n5), t3 = f4add(n6, n7);
        float4 acc1 = f4add(f4add(t0, t1), f4add(t2, t3));

        float4 m0 = __ldg(&E[(size_t)gj[8]  * 32 + lane]);
        float4 m1 = __ldg(&E[(size_t)gj[9]  * 32 + lane]);
        float4 m2 = __ldg(&E[(size_t)gj[10] * 32 + lane]);
        float4 m3 = __ldg(&E[(size_t)gj[11] * 32 + lane]);
        float4 m4 = __ldg(&E[(size_t)gj[12] * 32 + lane]);
        float4 m5 = __ldg(&E[(size_t)gj[13] * 32 + lane]);
        float4 m6 = __ldg(&E[(size_t)gj[14] * 32 + lane]);
        float4 m7 = __ldg(&E[(size_t)gj[15] * 32 + lane]);
        float4 u0 = f4add(m0, m1), u1 = f4add(m2, m3);
        float4 u2 = f4add(m4, m5), u3 = f4add(m6, m7);
        float4 acc2 = f4add(f4add(u0, u1), f4add(u2, u3));

        float4 acc = f4add(acc1, acc2);

        uint4 ts, tn;
        ts.x = f2tf32(v0.x); ts.y = f2tf32(v0.y); ts.z = f2tf32(v0.z); ts.w = f2tf32(v0.w);
        tn.x = f2tf32(acc.x * inv); tn.y = f2tf32(acc.y * inv);
        tn.z = f2tf32(acc.z * inv); tn.w = f2tf32(acc.w * inv);
        size_t row = (size_t)base + r;
        *(uint4*)&g_X0[row * 256 + lane * 4]       = ts;
        *(uint4*)&g_X0[row * 256 + 128 + lane * 4] = tn;
    }
}

// ---------------- gemm0: tf32 MMA, 3-stage cp.async, 1 sync/iter -----------
#define AS_W (128 * 36)
#define BS_W (32 * 132)
#define STG_W (AS_W + BS_W)                       // 8832 words per stage
#define GEMM0_SM_BYTES (3 * STG_W * 4)            // 105984

__global__ __launch_bounds__(256, 2) void gemm0_tc_kernel() {
    extern __shared__ uint32_t sm[];

    const int tid  = threadIdx.x;
    const int l    = tid & 31;
    const int lm   = l >> 2;
    const int lk   = l & 3;
    const int wid  = tid >> 5;
    const int wm   = wid >> 2;
    const int wn   = wid & 3;
    const size_t block_row = (size_t)blockIdx.x * 128;
    const uint32_t* __restrict__ A = g_X0 + block_row * 256;
    const uint32_t* __restrict__ B = g_W0T;

    auto stageA = [&](int s) -> uint32_t (*)[36] {
        return (uint32_t (*)[36])(sm + s * STG_W);
    };
    auto stageB = [&](int s) -> uint32_t (*)[132] {
        return (uint32_t (*)[132])(sm + s * STG_W + AS_W);
    };

    auto prefetch = [&](int chunk) {
        const int s = chunk % 3;
        const int k0 = chunk * 32;
        uint32_t (*As)[36] = stageA(s);
        uint32_t (*Bs)[132] = stageB(s);
        #pragma unroll
        for (int it = 0; it < 4; it++) {
            int idx = it * 256 + tid;
            int row = idx >> 3;
            int c4  = idx & 7;
            uint32_t d = smem_u32(&As[row][c4 * 4]);
            const uint32_t* src = A + (size_t)row * 256 + k0 + c4 * 4;
            asm volatile("cp.async.cg.shared.global [%0], [%1], 16;" :: "r"(d), "l"(src));
        }
        #pragma unroll
        for (int it = 0; it < 4; it++) {
            int idx = it * 256 + tid;
            int kk = idx >> 5;
            int n4 = idx & 31;
            uint32_t d = smem_u32(&Bs[kk][n4 * 4]);
            const uint32_t* src = B + (size_t)(k0 + kk) * 128 + n4 * 4;
            asm volatile("cp.async.cg.shared.global [%0], [%1], 16;" :: "r"(d), "l"(src));
        }
        asm volatile("cp.async.commit_group;" ::: "memory");
    };

    float acc[4][4][4];
    #pragma unroll
    for (int i = 0; i < 4; i++)
        #pragma unroll
        for (int j = 0; j < 4; j++)
            #pragma unroll
            for (int c = 0; c < 4; c++) acc[i][j][c] = 0.f;

    prefetch(0);
    prefetch(1);

    #pragma unroll
    for (int ch = 0; ch < 8; ch++) {
        const int s = ch % 3;
        if (ch < 7) {
            asm volatile("cp.async.wait_group 1;" ::: "memory");
        } else {
            asm volatile("cp.async.wait_group 0;" ::: "memory");
        }
        __syncthreads();
        if (ch + 2 < 8) prefetch(ch + 2);   // writes buffer (ch+2)%3 — free

        uint32_t (*As)[36] = stageA(s);
        uint32_t (*Bs)[132] = stageB(s);
        #pragma unroll
        for (int kk = 0; kk < 4; kk++) {
            const int k8 = kk * 8;
            uint32_t af[4][4], bf[4][2];
            #pragma unroll
            for (int mt = 0; mt < 4; mt++) {
                int mrow = wm * 64 + mt * 16 + lm;
                af[mt][0] = As[mrow    ][k8 + lk];
                af[mt][1] = As[mrow + 8][k8 + lk];
                af[mt][2] = As[mrow    ][k8 + lk + 4];
                af[mt][3] = As[mrow + 8][k8 + lk + 4];
            }
            #pragma unroll
            for (int nt = 0; nt < 4; nt++) {
                int ncol = wn * 32 + nt * 8 + lm;
                bf[nt][0] = Bs[k8 + lk    ][ncol];
                bf[nt][1] = Bs[k8 + lk + 4][ncol];
            }
            #pragma unroll
            for (int mt = 0; mt < 4; mt++)
                #pragma unroll
                for (int nt = 0; nt < 4; nt++)
                    mma_tf32(acc[mt][nt], af[mt][0], af[mt][1], af[mt][2], af[mt][3],
                             bf[nt][0], bf[nt][1]);
        }
    }

    float2* __restrict__ H2 = (float2*)g_H1;      // row stride = 64 float2
    #pragma unroll
    for (int nt = 0; nt < 4; nt++) {
        int col = wn * 32 + nt * 8 + lk * 2;
        float bv0 = g_b0[col], bv1 = g_b0[col + 1];
        #pragma unroll
        for (int mt = 0; mt < 4; mt++) {
            size_t row0 = block_row + wm * 64 + mt * 16 + lm;
            float2 v0 = make_float2(fmaxf(acc[mt][nt][0] + bv0, 0.f),
                                    fmaxf(acc[mt][nt][1] + bv1, 0.f));
            float2 v1 = make_float2(fmaxf(acc[mt][nt][2] + bv0, 0.f),
                                    fmaxf(acc[mt][nt][3] + bv1, 0.f));
            H2[row0 * 64 + (col >> 1)]       = v0;
            H2[(row0 + 8) * 64 + (col >> 1)] = v1;
        }
    }
}

// ---------------- layer-1 gather: register-batched, writes tf32 X1 ---------
__global__ __launch_bounds__(256) void gather1_kernel(const int* __restrict__ nbr1) {
    int warp = (blockIdx.x * blockDim.x + threadIdx.x) >> 5;
    int lane = threadIdx.x & 31;
    if (warp >= N_DST1) return;

    int nj = 0;
    if (lane < FANOUT) nj = nbr1[warp * FANOUT + lane];

    int gj[FANOUT];
    #pragma unroll
    for (int j = 0; j < FANOUT; j++) gj[j] = __shfl_sync(0xffffffffu, nj, j);

    const float4* H = (const float4*)g_H1;                // row stride = 32 float4
    float4 s  = __ldg(&H[(size_t)warp * 32 + lane]);
    float4 n0 = __ldg(&H[(size_t)gj[0] * 32 + lane]);
    float4 n1 = __ldg(&H[(size_t)gj[1] * 32 + lane]);
    float4 n2 = __ldg(&H[(size_t)gj[2] * 32 + lane]);
    float4 n3 = __ldg(&H[(size_t)gj[3] * 32 + lane]);
    float4 n4 = __ldg(&H[(size_t)gj[4] * 32 + lane]);
    float4 n5 = __ldg(&H[(size_t)gj[5] * 32 + lane]);
    float4 n6 = __ldg(&H[(size_t)gj[6] * 32 + lane]);
    float4 n7 = __ldg(&H[(size_t)gj[7] * 32 + lane]);
    float4 t0 = f4add(n0, n1), t1 = f4add(n2, n3);
    float4 t2 = f4add(n4, n5), t3 = f4add(n6, n7);
    float4 acc1 = f4add(f4add(t0, t1), f4add(t2, t3));

    float4 m0 = __ldg(&H[(size_t)gj[8]  * 32 + lane]);
    float4 m1 = __ldg(&H[(size_t)gj[9]  * 32 + lane]);
    float4 m2 = __ldg(&H[(size_t)gj[10] * 32 + lane]);
    float4 m3 = __ldg(&H[(size_t)gj[11] * 32 + lane]);
    float4 m4 = __ldg(&H[(size_t)gj[12] * 32 + lane]);
    float4 m5 = __ldg(&H[(size_t)gj[13] * 32 + lane]);
    float4 m6 = __ldg(&H[(size_t)gj[14] * 32 + lane]);
    float4 m7 = __ldg(&H[(size_t)gj[15] * 32 + lane]);
    float4 u0 = f4add(m0, m1), u1 = f4add(m2, m3);
    float4 u2 = f4add(m4, m5), u3 = f4add(m6, m7);
    float4 acc2 = f4add(f4add(u0, u1), f4add(u2, u3));

    float4 acc = f4add(acc1, acc2);
    const float inv = 1.0f / (float)FANOUT;

    uint4 ts, tn;
    ts.x = f2tf32(s.x); ts.y = f2tf32(s.y); ts.z = f2tf32(s.z); ts.w = f2tf32(s.w);
    tn.x = f2tf32(acc.x * inv); tn.y = f2tf32(acc.y * inv);
    tn.z = f2tf32(acc.z * inv); tn.w = f2tf32(acc.w * inv);
    *(uint4*)&g_X1[(size_t)warp * 256 + lane * 4]       = ts;
    *(uint4*)&g_X1[(size_t)warp * 256 + 128 + lane * 4] = tn;
}

// ---------------- gemm1 v3 (tensor cores): out = X1 @ WfT + bf -------------
// M=4096, N=64, K=256. 128 CTAs x 32 rows; full B + full A tile staged once,
// ONE sync, then all 32 k-steps sync-free. 8 warps 2(m) x 4(n), tile 16x16.
#define G1_AS_W (32 * 260)                 // 8320 words
#define G1_BS_W (256 * 68)                 // 17408 words
#define GEMM1_SM_BYTES ((G1_AS_W + G1_BS_W) * 4)   // 102912

__global__ __launch_bounds__(256) void gemm1_tc_kernel(float* __restrict__ C) {
    extern __shared__ uint32_t sm1[];
    uint32_t (*As)[260] = (uint32_t (*)[260])sm1;
    uint32_t (*Bs)[68]  = (uint32_t (*)[68])(sm1 + G1_AS_W);

    const int tid  = threadIdx.x;
    const int l    = tid & 31;
    const int lm   = l >> 2;
    const int lk   = l & 3;
    const int wid  = tid >> 5;
    const int wm   = wid >> 2;          // 0..1 -> rows wm*16..
    const int wn   = wid & 3;           // 0..3 -> cols wn*16..
    const size_t block_row = (size_t)blockIdx.x * 32;
    const uint32_t* __restrict__ A = g_X1 + block_row * 256;
    const uint32_t* __restrict__ B = g_WfT;

    // stage full A tile: 32 rows x 256 k = 2048 uint4 -> 8 iters
    #pragma unroll
    for (int it = 0; it < 8; it++) {
        int idx = it * 256 + tid;
        int row = idx >> 6;            // /64
        int c4  = idx & 63;
        *(uint4*)&As[row][c4 * 4] = *(const uint4*)(A + (size_t)row * 256 + c4 * 4);
    }
    // stage full B: 256 k x 64 n = 4096 uint4 -> 16 iters
    #pragma unroll
    for (int it = 0; it < 16; it++) {
        int idx = it * 256 + tid;
        int kk = idx >> 4;
        int n4 = idx & 15;
        *(uint4*)&Bs[kk][n4 * 4] = *(const uint4*)(B + (size_t)kk * 64 + n4 * 4);
    }
    __syncthreads();

    float acc[2][4];
    #pragma unroll
    for (int j = 0; j < 2; j++)
        #pragma unroll
        for (int c = 0; c < 4; c++) acc[j][c] = 0.f;

    const int mrow = wm * 16 + lm;
    #pragma unroll
    for (int k8 = 0; k8 < 256; k8 += 8) {
        uint32_t a0 = As[mrow    ][k8 + lk];
        uint32_t a1 = As[mrow + 8][k8 + lk];
        uint32_t a2 = As[mrow    ][k8 + lk + 4];
        uint32_t a3 = As[mrow + 8][k8 + lk + 4];
        #pragma unroll
        for (int nt = 0; nt < 2; nt++) {
            int ncol = wn * 16 + nt * 8 + lm;
            uint32_t b0 = Bs[k8 + lk    ][ncol];
            uint32_t b1 = Bs[k8 + lk + 4][ncol];
            mma_tf32(acc[nt], a0, a1, a2, a3, b0, b1);
        }
    }

    // epilogue: +bf, write float2
    #pragma unroll
    for (int nt = 0; nt < 2; nt++) {
        int col = wn * 16 + nt * 8 + lk * 2;
        float bv0 = g_bf[col], bv1 = g_bf[col + 1];
        size_t row0 = block_row + wm * 16 + lm;
        float2* c0 = (float2*)(C + row0 * 64 + col);
        float2* c1 = (float2*)(C + (row0 + 8) * 64 + col);
        *c0 = make_float2(acc[nt][0] + bv0, acc[nt][1] + bv1);
        *c1 = make_float2(acc[nt][2] + bv0, acc[nt][3] + bv1);
    }
}

// ---------------- launch ---------------------------------------------------
extern "C" void kernel_launch(void* const* d_in, const int* in_sizes, int n_in,
                              void* d_out, int out_size) {
    const float* emb      = (const float*)d_in[0];
    const float* Ws0      = (const float*)d_in[1];
    const float* bs0      = (const float*)d_in[2];
    const float* Wn0      = (const float*)d_in[3];
    const float* bn0      = (const float*)d_in[4];
    const float* Ws1      = (const float*)d_in[5];
    const float* bs1      = (const float*)d_in[6];
    const float* Wn1      = (const float*)d_in[7];
    const float* bn1      = (const float*)d_in[8];
    const float* Wout     = (const float*)d_in[9];
    const float* bout     = (const float*)d_in[10];
    const int*   in_nodes = (const int*)d_in[11];
    const int*   nbr0     = (const int*)d_in[12];
    const int*   nbr1     = (const int*)d_in[13];
    float* out = (float*)d_out;

    cudaFuncSetAttribute(gemm0_tc_kernel,
                         cudaFuncAttributeMaxDynamicSharedMemorySize, GEMM0_SM_BYTES);
    cudaFuncSetAttribute(gemm1_tc_kernel,
                         cudaFuncAttributeMaxDynamicSharedMemorySize, GEMM1_SM_BYTES);

    // layer 0: gather + weight prep in ONE launch, then 3-stage tc GEMM
    gather0_prep_kernel<<<G0_BLOCKS + PREP_BLOCKS, 256>>>(
        emb, in_nodes, nbr0,
        Ws0, bs0, Wn0, bn0, Ws1, bs1, Wn1, bn1, Wout, bout);
    gemm0_tc_kernel<<<N_DST0 / 128, 256, GEMM0_SM_BYTES>>>();

    // layer 1 gather (tf32 out), then tensor-core output GEMM (one wave)
    gather1_kernel<<<(N_DST1 * 32) / 256, 256>>>(nbr1);
    gemm1_tc_kernel<<<N_DST1 / 32, 256, GEMM1_SM_BYTES>>>(out);
}

// round 14
// speedup vs baseline: 1.2079x; 1.0051x over previous
#include <cuda_runtime.h>
#include <cuda_bf16.h>
#include <cstdint>

// Problem dims
#define NUM_NODES 1000000
#define HIDDEN    128
#define OUT_DIM   64
#define FANOUT    16
#define N_SRC0    1048576
#define N_DST0    65536
#define N_DST1    4096

#define G0_BLOCKS (N_DST0 / 64)          // 1024 gather CTAs
#define PREP_BLOCKS 192                  // 128 (W0) + 64 (Wf)

// ---------------- scratch (static device globals; no allocations) ----------
__device__ uint32_t g_X0[(size_t)N_DST0 * 256];   // tf32 BITS [self|mean]
__device__ float    g_H1[(size_t)N_DST0 * 128];   // layer-0 output (post-ReLU)
__device__ uint32_t g_W0T[256 * 128];             // tf32 BITS: [k][n] = cat(Ws0,Wn0)^T
__device__ float    g_b0[128];                    // b_self0 + b_neigh0
__device__ uint32_t g_WfT[256 * 64];              // tf32 BITS: (W_out @ cat(Ws1,Wn1))^T
__device__ float    g_bf[64];                     // W_out @ (bs1+bn1) + b_out

// ---------------- helpers --------------------------------------------------
__device__ __forceinline__ uint32_t f2tf32(float f) {
    uint32_t r; asm("cvt.rna.tf32.f32 %0, %1;" : "=r"(r) : "f"(f)); return r;
}

__device__ __forceinline__ float4 f4add(float4 a, float4 b) {
    return make_float4(a.x + b.x, a.y + b.y, a.z + b.z, a.w + b.w);
}

__device__ __forceinline__ uint32_t smem_u32(const void* p) {
    uint32_t a;
    asm("{ .reg .u64 t; cvta.to.shared.u64 t, %1; cvt.u32.u64 %0, t; }" : "=r"(a) : "l"(p));
    return a;
}

// streaming (evict-first) 16B store — keeps emb resident in L2
__device__ __forceinline__ void stg_cs_v4(uint32_t* p, uint4 v) {
    asm volatile("st.global.cs.v4.u32 [%0], {%1,%2,%3,%4};"
                 :: "l"(p), "r"(v.x), "r"(v.y), "r"(v.z), "r"(v.w) : "memory");
}

__device__ __forceinline__ void mma_tf32(float c[4],
                                         uint32_t a0, uint32_t a1, uint32_t a2, uint32_t a3,
                                         uint32_t b0, uint32_t b1) {
    asm volatile(
        "mma.sync.aligned.m16n8k8.row.col.f32.tf32.tf32.f32 "
        "{%0,%1,%2,%3}, {%4,%5,%6,%7}, {%8,%9}, {%0,%1,%2,%3};"
        : "+f"(c[0]), "+f"(c[1]), "+f"(c[2]), "+f"(c[3])
        : "r"(a0), "r"(a1), "r"(a2), "r"(a3), "r"(b0), "r"(b1));
}

// ---------------- gather0 + prep, one launch --------------------------------
__global__ __launch_bounds__(256, 4) void gather0_prep_kernel(
    const float* __restrict__ emb, const int* __restrict__ input_nodes,
    const int* __restrict__ nbr0,
    const float* __restrict__ Ws0, const float* __restrict__ bs0,
    const float* __restrict__ Wn0, const float* __restrict__ bn0,
    const float* __restrict__ Ws1, const float* __restrict__ bs1,
    const float* __restrict__ Wn1, const float* __restrict__ bn1,
    const float* __restrict__ Wout, const float* __restrict__ bout) {

    if (blockIdx.x >= G0_BLOCKS) {
        // ---------------- prep path ----------------
        const int pb = blockIdx.x - G0_BLOCKS;
        if (pb < 128) {
            int idx = pb * 256 + threadIdx.x;              // 0..32767
            int k = idx >> 7;
            int n = idx & 127;
            float v = (k < 128) ? Ws0[n * 128 + k] : Wn0[n * 128 + (k - 128)];
            g_W0T[idx] = f2tf32(v);
            if (idx < 128) g_b0[idx] = bs0[idx] + bn0[idx];
        } else {
            int idx = (pb - 128) * 256 + threadIdx.x;      // 0..16383
            int k = idx >> 6;
            int n = idx & 63;
            float acc = 0.f;
            if (k < 128) {
                #pragma unroll 4
                for (int r = 0; r < 128; r++) acc += Wout[n * 128 + r] * Ws1[r * 128 + k];
            } else {
                int kk = k - 128;
                #pragma unroll 4
                for (int r = 0; r < 128; r++) acc += Wout[n * 128 + r] * Wn1[r * 128 + kk];
            }
            g_WfT[k * 64 + n] = f2tf32(acc);
            if (idx < 64) {
                float a2 = bout[idx];
                #pragma unroll 4
                for (int r = 0; r < 128; r++) a2 += Wout[idx * 128 + r] * (bs1[r] + bn1[r]);
                g_bf[idx] = a2;
            }
        }
        return;
    }

    // ---------------- gather path (register-batched, proven) ----------------
    __shared__ int s_idx[64 * FANOUT];
    __shared__ int s_self[64];

    const int tid  = threadIdx.x;
    const int lane = tid & 31;
    const int wid  = tid >> 5;
    const int base = blockIdx.x * 64;

    #pragma unroll
    for (int it = 0; it < 4; it++) {
        int i = it * 256 + tid;
        s_idx[i] = input_nodes[nbr0[(size_t)base * FANOUT + i]];
    }
    if (tid < 64) s_self[tid] = input_nodes[base + tid];
    __syncthreads();

    const float4* E = (const float4*)emb;        // row stride = 32 float4
    const float inv = 1.0f / (float)FANOUT;

    #pragma unroll 2
    for (int rr = 0; rr < 8; rr++) {
        const int r = wid * 8 + rr;

        int gj[FANOUT];
        #pragma unroll
        for (int j = 0; j < FANOUT; j++) gj[j] = s_idx[r * FANOUT + j];
        const int gs = s_self[r];

        float4 v0 = __ldg(&E[(size_t)gs * 32 + lane]);
        float4 n0 = __ldg(&E[(size_t)gj[0] * 32 + lane]);
        float4 n1 = __ldg(&E[(size_t)gj[1] * 32 + lane]);
        float4 n2 = __ldg(&E[(size_t)gj[2] * 32 + lane]);
        float4 n3 = __ldg(&E[(size_t)gj[3] * 32 + lane]);
        float4 n4 = __ldg(&E[(size_t)gj[4] * 32 + lane]);
        float4 n5 = __ldg(&E[(size_t)gj[5] * 32 + lane]);
        float4 n6 = __ldg(&E[(size_t)gj[6] * 32 + lane]);
        float4 n7 = __ldg(&E[(size_t)gj[7] * 32 + lane]);
        float4 t0 = f4add(n0, n1), t1 = f4add(n2, n3);
        float4 t2 = f4add(n4, n5), t3 = f4add(n6, n7);
        float4 acc1 = f4add(f4add(t0, t1), f4add(t2, t3));

        float4 m0 = __ldg(&E[(size_t)gj[8]  * 32 + lane]);
        float4 m1 = __ldg(&E[(size_t)gj[9]  * 32 + lane]);
        float4 m2 = __ldg(&E[(size_t)gj[10] * 32 + lane]);
        float4 m3 = __ldg(&E[(size_t)gj[11] * 32 + lane]);
        float4 m4 = __ldg(&E[(size_t)gj[12] * 32 + lane]);
        float4 m5 = __ldg(&E[(size_t)gj[13] * 32 + lane]);
        float4 m6 = __ldg(&E[(size_t)gj[14] * 32 + lane]);
        float4 m7 = __ldg(&E[(size_t)gj[15] * 32 + lane]);
        float4 u0 = f4add(m0, m1), u1 = f4add(m2, m3);
        float4 u2 = f4add(m4, m5), u3 = f4add(m6, m7);
        float4 acc2 = f4add(f4add(u0, u1), f4add(u2, u3));

        float4 acc = f4add(acc1, acc2);

        uint4 ts, tn;
        ts.x = f2tf32(v0.x); ts.y = f2tf32(v0.y); ts.z = f2tf32(v0.z); ts.w = f2tf32(v0.w);
        tn.x = f2tf32(acc.x * inv); tn.y = f2tf32(acc.y * inv);
        tn.z = f2tf32(acc.z * inv); tn.w = f2tf32(acc.w * inv);
        size_t row = (size_t)base + r;
        stg_cs_v4(&g_X0[row * 256 + lane * 4], ts);         // evict-first
        stg_cs_v4(&g_X0[row * 256 + 128 + lane * 4], tn);   // evict-first
    }
}

// ---------------- gemm0: tf32 MMA, 3-stage cp.async, 1 sync/iter -----------
#define AS_W (128 * 36)
#define BS_W (32 * 132)
#define STG_W (AS_W + BS_W)                       // 8832 words per stage
#define GEMM0_SM_BYTES (3 * STG_W * 4)            // 105984

__global__ __launch_bounds__(256, 2) void gemm0_tc_kernel() {
    extern __shared__ uint32_t sm[];

    const int tid  = threadIdx.x;
    const int l    = tid & 31;
    const int lm   = l >> 2;
    const int lk   = l & 3;
    const int wid  = tid >> 5;
    const int wm   = wid >> 2;
    const int wn   = wid & 3;
    const size_t block_row = (size_t)blockIdx.x * 128;
    const uint32_t* __restrict__ A = g_X0 + block_row * 256;
    const uint32_t* __restrict__ B = g_W0T;

    auto stageA = [&](int s) -> uint32_t (*)[36] {
        return (uint32_t (*)[36])(sm + s * STG_W);
    };
    auto stageB = [&](int s) -> uint32_t (*)[132] {
        return (uint32_t (*)[132])(sm + s * STG_W + AS_W);
    };

    auto prefetch = [&](int chunk) {
        const int s = chunk % 3;
        const int k0 = chunk * 32;
        uint32_t (*As)[36] = stageA(s);
        uint32_t (*Bs)[132] = stageB(s);
        #pragma unroll
        for (int it = 0; it < 4; it++) {
            int idx = it * 256 + tid;
            int row = idx >> 3;
            int c4  = idx & 7;
            uint32_t d = smem_u32(&As[row][c4 * 4]);
            const uint32_t* src = A + (size_t)row * 256 + k0 + c4 * 4;
            asm volatile("cp.async.cg.shared.global [%0], [%1], 16;" :: "r"(d), "l"(src));
        }
        #pragma unroll
        for (int it = 0; it < 4; it++) {
            int idx = it * 256 + tid;
            int kk = idx >> 5;
            int n4 = idx & 31;
            uint32_t d = smem_u32(&Bs[kk][n4 * 4]);
            const uint32_t* src = B + (size_t)(k0 + kk) * 128 + n4 * 4;
            asm volatile("cp.async.cg.shared.global [%0], [%1], 16;" :: "r"(d), "l"(src));
        }
        asm volatile("cp.async.commit_group;" ::: "memory");
    };

    float acc[4][4][4];
    #pragma unroll
    for (int i = 0; i < 4; i++)
        #pragma unroll
        for (int j = 0; j < 4; j++)
            #pragma unroll
            for (int c = 0; c < 4; c++) acc[i][j][c] = 0.f;

    prefetch(0);
    prefetch(1);

    #pragma unroll
    for (int ch = 0; ch < 8; ch++) {
        const int s = ch % 3;
        if (ch < 7) {
            asm volatile("cp.async.wait_group 1;" ::: "memory");
        } else {
            asm volatile("cp.async.wait_group 0;" ::: "memory");
        }
        __syncthreads();
        if (ch + 2 < 8) prefetch(ch + 2);   // writes buffer (ch+2)%3 — free

        uint32_t (*As)[36] = stageA(s);
        uint32_t (*Bs)[132] = stageB(s);
        #pragma unroll
        for (int kk = 0; kk < 4; kk++) {
            const int k8 = kk * 8;
            uint32_t af[4][4], bf[4][2];
            #pragma unroll
            for (int mt = 0; mt < 4; mt++) {
                int mrow = wm * 64 + mt * 16 + lm;
                af[mt][0] = As[mrow    ][k8 + lk];
                af[mt][1] = As[mrow + 8][k8 + lk];
                af[mt][2] = As[mrow    ][k8 + lk + 4];
                af[mt][3] = As[mrow + 8][k8 + lk + 4];
            }
            #pragma unroll
            for (int nt = 0; nt < 4; nt++) {
                int ncol = wn * 32 + nt * 8 + lm;
                bf[nt][0] = Bs[k8 + lk    ][ncol];
                bf[nt][1] = Bs[k8 + lk + 4][ncol];
            }
            #pragma unroll
            for (int mt = 0; mt < 4; mt++)
                #pragma unroll
                for (int nt = 0; nt < 4; nt++)
                    mma_tf32(acc[mt][nt], af[mt][0], af[mt][1], af[mt][2], af[mt][3],
                             bf[nt][0], bf[nt][1]);
        }
    }

    float2* __restrict__ H2 = (float2*)g_H1;      // row stride = 64 float2
    #pragma unroll
    for (int nt = 0; nt < 4; nt++) {
        int col = wn * 32 + nt * 8 + lk * 2;
        float bv0 = g_b0[col], bv1 = g_b0[col + 1];
        #pragma unroll
        for (int mt = 0; mt < 4; mt++) {
            size_t row0 = block_row + wm * 64 + mt * 16 + lm;
            float2 v0 = make_float2(fmaxf(acc[mt][nt][0] + bv0, 0.f),
                                    fmaxf(acc[mt][nt][1] + bv1, 0.f));
            float2 v1 = make_float2(fmaxf(acc[mt][nt][2] + bv0, 0.f),
                                    fmaxf(acc[mt][nt][3] + bv1, 0.f));
            H2[row0 * 64 + (col >> 1)]       = v0;
            H2[(row0 + 8) * 64 + (col >> 1)] = v1;
        }
    }
}

// ---------------- layer-1 fused: gather + mean + tf32 MMA + bias -----------
// 128 CTAs x 32 rows. WfT streams in via cp.async UNDER the gather phase;
// gather writes tf32 rows straight into the smem A tile; one sync; sync-free
// 32-step MMA; bias epilogue. No X1 round trip, one launch instead of two.
#define G1_AS_W (32 * 260)                 // 8320 words
#define G1_BS_W (256 * 68)                 // 17408 words
#define GEMM1_SM_BYTES ((G1_AS_W + G1_BS_W) * 4)   // 102912

__global__ __launch_bounds__(256) void layer1_fused_kernel(
    const int* __restrict__ nbr1, float* __restrict__ C) {
    extern __shared__ uint32_t sm1[];
    uint32_t (*As)[260] = (uint32_t (*)[260])sm1;
    uint32_t (*Bs)[68]  = (uint32_t (*)[68])(sm1 + G1_AS_W);

    const int tid  = threadIdx.x;
    const int l    = tid & 31;
    const int lane = l;
    const int wid  = tid >> 5;
    const size_t block_row = (size_t)blockIdx.x * 32;

    // --- issue cp.async for full WfT (streams under the gather) ---
    const uint32_t* __restrict__ B = g_WfT;
    #pragma unroll
    for (int it = 0; it < 16; it++) {
        int idx = it * 256 + tid;
        int kk = idx >> 4;
        int n4 = idx & 15;
        uint32_t d = smem_u32(&Bs[kk][n4 * 4]);
        asm volatile("cp.async.cg.shared.global [%0], [%1], 16;"
                     :: "r"(d), "l"(B + (size_t)kk * 64 + n4 * 4));
    }
    asm volatile("cp.async.commit_group;" ::: "memory");

    // --- gather phase: 4 rows per warp, register-batched ---
    const float4* H = (const float4*)g_H1;          // row stride = 32 float4
    const float inv = 1.0f / (float)FANOUT;
    #pragma unroll
    for (int rr = 0; rr < 4; rr++) {
        const int r = wid * 4 + rr;
        const size_t grow = block_row + r;
        int nj = (lane < FANOUT) ? nbr1[grow * FANOUT + lane] : 0;
        int gj[FANOUT];
        #pragma unroll
        for (int j = 0; j < FANOUT; j++) gj[j] = __shfl_sync(0xffffffffu, nj, j);

        float4 s  = __ldg(&H[grow * 32 + lane]);
        float4 n0 = __ldg(&H[(size_t)gj[0] * 32 + lane]);
        float4 n1 = __ldg(&H[(size_t)gj[1] * 32 + lane]);
        float4 n2 = __ldg(&H[(size_t)gj[2] * 32 + lane]);
        float4 n3 = __ldg(&H[(size_t)gj[3] * 32 + lane]);
        float4 n4 = __ldg(&H[(size_t)gj[4] * 32 + lane]);
        float4 n5 = __ldg(&H[(size_t)gj[5] * 32 + lane]);
        float4 n6 = __ldg(&H[(size_t)gj[6] * 32 + lane]);
        float4 n7 = __ldg(&H[(size_t)gj[7] * 32 + lane]);
        float4 t0 = f4add(n0, n1), t1 = f4add(n2, n3);
        float4 t2 = f4add(n4, n5), t3 = f4add(n6, n7);
        float4 acc1 = f4add(f4add(t0, t1), f4add(t2, t3));

        float4 m0 = __ldg(&H[(size_t)gj[8]  * 32 + lane]);
        float4 m1 = __ldg(&H[(size_t)gj[9]  * 32 + lane]);
        float4 m2 = __ldg(&H[(size_t)gj[10] * 32 + lane]);
        float4 m3 = __ldg(&H[(size_t)gj[11] * 32 + lane]);
        float4 m4 = __ldg(&H[(size_t)gj[12] * 32 + lane]);
        float4 m5 = __ldg(&H[(size_t)gj[13] * 32 + lane]);
        float4 m6 = __ldg(&H[(size_t)gj[14] * 32 + lane]);
        float4 m7 = __ldg(&H[(size_t)gj[15] * 32 + lane]);
        float4 u0 = f4add(m0, m1), u1 = f4add(m2, m3);
        float4 u2 = f4add(m4, m5), u3 = f4add(m6, m7);
        float4 acc2 = f4add(f4add(u0, u1), f4add(u2, u3));

        float4 acc = f4add(acc1, acc2);

        uint4 ts, tn;
        ts.x = f2tf32(s.x); ts.y = f2tf32(s.y); ts.z = f2tf32(s.z); ts.w = f2tf32(s.w);
        tn.x = f2tf32(acc.x * inv); tn.y = f2tf32(acc.y * inv);
        tn.z = f2tf32(acc.z * inv); tn.w = f2tf32(acc.w * inv);
        *(uint4*)&As[r][lane * 4]       = ts;
        *(uint4*)&As[r][128 + lane * 4] = tn;
    }

    asm volatile("cp.async.wait_group 0;" ::: "memory");
    __syncthreads();

    // --- MMA phase: 8 warps 2(m) x 4(n), warp tile 16x16, sync-free ---
    const int lm = l >> 2;
    const int lk = l & 3;
    const int wm = wid >> 2;
    const int wn = wid & 3;

    float acc[2][4];
    #pragma unroll
    for (int j = 0; j < 2; j++)
        #pragma unroll
        for (int c = 0; c < 4; c++) acc[j][c] = 0.f;

    const int mrow = wm * 16 + lm;
    #pragma unroll
    for (int k8 = 0; k8 < 256; k8 += 8) {
        uint32_t a0 = As[mrow    ][k8 + lk];
        uint32_t a1 = As[mrow + 8][k8 + lk];
        uint32_t a2 = As[mrow    ][k8 + lk + 4];
        uint32_t a3 = As[mrow + 8][k8 + lk + 4];
        #pragma unroll
        for (int nt = 0; nt < 2; nt++) {
            int ncol = wn * 16 + nt * 8 + lm;
            uint32_t b0 = Bs[k8 + lk    ][ncol];
            uint32_t b1 = Bs[k8 + lk + 4][ncol];
            mma_tf32(acc[nt], a0, a1, a2, a3, b0, b1);
        }
    }

    // epilogue: +bf, write float2
    #pragma unroll
    for (int nt = 0; nt < 2; nt++) {
        int col = wn * 16 + nt * 8 + lk * 2;
        float bv0 = g_bf[col], bv1 = g_bf[col + 1];
        size_t row0 = block_row + wm * 16 + lm;
        float2* c0 = (float2*)(C + row0 * 64 + col);
        float2* c1 = (float2*)(C + (row0 + 8) * 64 + col);
        *c0 = make_float2(acc[nt][0] + bv0, acc[nt][1] + bv1);
        *c1 = make_float2(acc[nt][2] + bv0, acc[nt][3] + bv1);
    }
}

// ---------------- launch ---------------------------------------------------
extern "C" void kernel_launch(void* const* d_in, const int* in_sizes, int n_in,
                              void* d_out, int out_size) {
    const float* emb      = (const float*)d_in[0];
    const float* Ws0      = (const float*)d_in[1];
    const float* bs0      = (const float*)d_in[2];
    const float* Wn0      = (const float*)d_in[3];
    const float* bn0      = (const float*)d_in[4];
    const float* Ws1      = (const float*)d_in[5];
    const float* bs1      = (const float*)d_in[6];
    const float* Wn1      = (const float*)d_in[7];
    const float* bn1      = (const float*)d_in[8];
    const float* Wout     = (const float*)d_in[9];
    const float* bout     = (const float*)d_in[10];
    const int*   in_nodes = (const int*)d_in[11];
    const int*   nbr0     = (const int*)d_in[12];
    const int*   nbr1     = (const int*)d_in[13];
    float* out = (float*)d_out;

    cudaFuncSetAttribute(gemm0_tc_kernel,
                         cudaFuncAttributeMaxDynamicSharedMemorySize, GEMM0_SM_BYTES);
    cudaFuncSetAttribute(layer1_fused_kernel,
                         cudaFuncAttributeMaxDynamicSharedMemorySize, GEMM1_SM_BYTES);

    // layer 0: gather + weight prep in ONE launch, then 3-stage tc GEMM
    gather0_prep_kernel<<<G0_BLOCKS + PREP_BLOCKS, 256>>>(
        emb, in_nodes, nbr0,
        Ws0, bs0, Wn0, bn0, Ws1, bs1, Wn1, bn1, Wout, bout);
    gemm0_tc_kernel<<<N_DST0 / 128, 256, GEMM0_SM_BYTES>>>();

    // layer 1: gather + output GEMM fully fused (one launch)
    layer1_fused_kernel<<<N_DST1 / 32, 256, GEMM1_SM_BYTES>>>(nbr1, out);
}

// round 15
// speedup vs baseline: 1.3594x; 1.1255x over previous
#include <cuda_runtime.h>
#include <cuda_fp16.h>
#include <cuda_bf16.h>
#include <cstdint>

// Problem dims
#define NUM_NODES 1000000
#define HIDDEN    128
#define OUT_DIM   64
#define FANOUT    16
#define N_SRC0    1048576
#define N_DST0    65536
#define N_DST1    4096

#define G0_BLOCKS (N_DST0 / 64)          // 1024 gather CTAs
#define PREP_BLOCKS 128                  // 64 (W0 fp16 pack) + 64 (Wf)

// ---------------- scratch (static device globals; no allocations) ----------
__device__ uint32_t g_X0[(size_t)N_DST0 * 128];   // fp16x2 pairs [self(64w)|mean(64w)]
__device__ float    g_H1[(size_t)N_DST0 * 128];   // layer-0 output (post-ReLU)
__device__ uint32_t g_W0T[128 * 128];             // fp16x2: [kpair][n] of cat(Ws0,Wn0)^T
__device__ float    g_b0[128];                    // b_self0 + b_neigh0
__device__ uint32_t g_WfT[256 * 64];              // tf32 BITS: (W_out @ cat(Ws1,Wn1))^T
__device__ float    g_bf[64];                     // W_out @ (bs1+bn1) + b_out

// ---------------- helpers --------------------------------------------------
__device__ __forceinline__ uint32_t f2tf32(float f) {
    uint32_t r; asm("cvt.rna.tf32.f32 %0, %1;" : "=r"(r) : "f"(f)); return r;
}

__device__ __forceinline__ uint32_t packh2(float a, float b) {
    __half2 h = __floats2half2_rn(a, b);
    return *(uint32_t*)&h;
}

__device__ __forceinline__ float4 f4add(float4 a, float4 b) {
    return make_float4(a.x + b.x, a.y + b.y, a.z + b.z, a.w + b.w);
}

__device__ __forceinline__ uint32_t smem_u32(const void* p) {
    uint32_t a;
    asm("{ .reg .u64 t; cvta.to.shared.u64 t, %1; cvt.u32.u64 %0, t; }" : "=r"(a) : "l"(p));
    return a;
}

// streaming (evict-first) 8B store — keeps emb resident in L2
__device__ __forceinline__ void stg_cs_v2(uint32_t* p, uint32_t a, uint32_t b) {
    asm volatile("st.global.cs.v2.u32 [%0], {%1,%2};"
                 :: "l"(p), "r"(a), "r"(b) : "memory");
}

// fp16 MMA, fp32 accumulate: m16n8k16
__device__ __forceinline__ void mma_f16(float c[4],
                                        uint32_t a0, uint32_t a1, uint32_t a2, uint32_t a3,
                                        uint32_t b0, uint32_t b1) {
    asm volatile(
        "mma.sync.aligned.m16n8k16.row.col.f32.f16.f16.f32 "
        "{%0,%1,%2,%3}, {%4,%5,%6,%7}, {%8,%9}, {%0,%1,%2,%3};"
        : "+f"(c[0]), "+f"(c[1]), "+f"(c[2]), "+f"(c[3])
        : "r"(a0), "r"(a1), "r"(a2), "r"(a3), "r"(b0), "r"(b1));
}

// tf32 MMA (layer-1 path, unchanged)
__device__ __forceinline__ void mma_tf32(float c[4],
                                         uint32_t a0, uint32_t a1, uint32_t a2, uint32_t a3,
                                         uint32_t b0, uint32_t b1) {
    asm volatile(
        "mma.sync.aligned.m16n8k8.row.col.f32.tf32.tf32.f32 "
        "{%0,%1,%2,%3}, {%4,%5,%6,%7}, {%8,%9}, {%0,%1,%2,%3};"
        : "+f"(c[0]), "+f"(c[1]), "+f"(c[2]), "+f"(c[3])
        : "r"(a0), "r"(a1), "r"(a2), "r"(a3), "r"(b0), "r"(b1));
}

// ---------------- gather0 + prep, one launch --------------------------------
__global__ __launch_bounds__(256, 4) void gather0_prep_kernel(
    const float* __restrict__ emb, const int* __restrict__ input_nodes,
    const int* __restrict__ nbr0,
    const float* __restrict__ Ws0, const float* __restrict__ bs0,
    const float* __restrict__ Wn0, const float* __restrict__ bn0,
    const float* __restrict__ Ws1, const float* __restrict__ bs1,
    const float* __restrict__ Wn1, const float* __restrict__ bn1,
    const float* __restrict__ Wout, const float* __restrict__ bout) {

    if (blockIdx.x >= G0_BLOCKS) {
        // ---------------- prep path ----------------
        const int pb = blockIdx.x - G0_BLOCKS;
        if (pb < 64) {
            // W0 fp16 pack: [kpair][n], word = (W[2kp][n], W[2kp+1][n])
            int idx = pb * 256 + threadIdx.x;              // 0..16383
            int kp = idx >> 7;                             // 0..127
            int n  = idx & 127;
            int k0 = kp * 2, k1 = kp * 2 + 1;
            float w0 = (k0 < 128) ? Ws0[n * 128 + k0] : Wn0[n * 128 + (k0 - 128)];
            float w1 = (k1 < 128) ? Ws0[n * 128 + k1] : Wn0[n * 128 + (k1 - 128)];
            g_W0T[idx] = packh2(w0, w1);
            if (idx < 128) g_b0[idx] = bs0[idx] + bn0[idx];
        } else {
            int idx = (pb - 64) * 256 + threadIdx.x;       // 0..16383
            int k = idx >> 6;
            int n = idx & 63;
            float acc = 0.f;
            if (k < 128) {
                #pragma unroll 4
                for (int r = 0; r < 128; r++) acc += Wout[n * 128 + r] * Ws1[r * 128 + k];
            } else {
                int kk = k - 128;
                #pragma unroll 4
                for (int r = 0; r < 128; r++) acc += Wout[n * 128 + r] * Wn1[r * 128 + kk];
            }
            g_WfT[k * 64 + n] = f2tf32(acc);
            if (idx < 64) {
                float a2 = bout[idx];
                #pragma unroll 4
                for (int r = 0; r < 128; r++) a2 += Wout[idx * 128 + r] * (bs1[r] + bn1[r]);
                g_bf[idx] = a2;
            }
        }
        return;
    }

    // ---------------- gather path (register-batched, proven) ----------------
    __shared__ int s_idx[64 * FANOUT];
    __shared__ int s_self[64];

    const int tid  = threadIdx.x;
    const int lane = tid & 31;
    const int wid  = tid >> 5;
    const int base = blockIdx.x * 64;

    #pragma unroll
    for (int it = 0; it < 4; it++) {
        int i = it * 256 + tid;
        s_idx[i] = input_nodes[nbr0[(size_t)base * FANOUT + i]];
    }
    if (tid < 64) s_self[tid] = input_nodes[base + tid];
    __syncthreads();

    const float4* E = (const float4*)emb;        // row stride = 32 float4
    const float inv = 1.0f / (float)FANOUT;

    #pragma unroll 2
    for (int rr = 0; rr < 8; rr++) {
        const int r = wid * 8 + rr;

        int gj[FANOUT];
        #pragma unroll
        for (int j = 0; j < FANOUT; j++) gj[j] = s_idx[r * FANOUT + j];
        const int gs = s_self[r];

        float4 v0 = __ldg(&E[(size_t)gs * 32 + lane]);
        float4 n0 = __ldg(&E[(size_t)gj[0] * 32 + lane]);
        float4 n1 = __ldg(&E[(size_t)gj[1] * 32 + lane]);
        float4 n2 = __ldg(&E[(size_t)gj[2] * 32 + lane]);
        float4 n3 = __ldg(&E[(size_t)gj[3] * 32 + lane]);
        float4 n4 = __ldg(&E[(size_t)gj[4] * 32 + lane]);
        float4 n5 = __ldg(&E[(size_t)gj[5] * 32 + lane]);
        float4 n6 = __ldg(&E[(size_t)gj[6] * 32 + lane]);
        float4 n7 = __ldg(&E[(size_t)gj[7] * 32 + lane]);
        float4 t0 = f4add(n0, n1), t1 = f4add(n2, n3);
        float4 t2 = f4add(n4, n5), t3 = f4add(n6, n7);
        float4 acc1 = f4add(f4add(t0, t1), f4add(t2, t3));

        float4 m0 = __ldg(&E[(size_t)gj[8]  * 32 + lane]);
        float4 m1 = __ldg(&E[(size_t)gj[9]  * 32 + lane]);
        float4 m2 = __ldg(&E[(size_t)gj[10] * 32 + lane]);
        float4 m3 = __ldg(&E[(size_t)gj[11] * 32 + lane]);
        float4 m4 = __ldg(&E[(size_t)gj[12] * 32 + lane]);
        float4 m5 = __ldg(&E[(size_t)gj[13] * 32 + lane]);
        float4 m6 = __ldg(&E[(size_t)gj[14] * 32 + lane]);
        float4 m7 = __ldg(&E[(size_t)gj[15] * 32 + lane]);
        float4 u0 = f4add(m0, m1), u1 = f4add(m2, m3);
        float4 u2 = f4add(m4, m5), u3 = f4add(m6, m7);
        float4 acc2 = f4add(f4add(u0, u1), f4add(u2, u3));

        float4 acc = f4add(acc1, acc2);

        // pack to fp16x2; X0 row = [self 64 words | mean 64 words]
        size_t row = (size_t)base + r;
        uint32_t s0 = packh2(v0.x, v0.y);
        uint32_t s1 = packh2(v0.z, v0.w);
        uint32_t q0 = packh2(acc.x * inv, acc.y * inv);
        uint32_t q1 = packh2(acc.z * inv, acc.w * inv);
        stg_cs_v2(&g_X0[row * 128 + lane * 2], s0, s1);          // evict-first
        stg_cs_v2(&g_X0[row * 128 + 64 + lane * 2], q0, q1);     // evict-first
    }
}

// ---------------- gemm0: fp16 MMA (fp32 acc), 3-stage cp.async -------------
// g_H1 = relu(X0 @ W0T + b0).  M=65536, N=128, K=256(halves)=128 words.
// 128x128 CTA tile, chunk = 32 word-cols (k=64), 4 chunks, 8 warps 2m x 4n.
#define AS_W (128 * 36)
#define BS_W (32 * 132)
#define STG_W (AS_W + BS_W)                       // 8832 words per stage
#define GEMM0_SM_BYTES (3 * STG_W * 4)            // 105984

__global__ __launch_bounds__(256, 2) void gemm0_tc_kernel() {
    extern __shared__ uint32_t sm[];

    const int tid  = threadIdx.x;
    const int l    = tid & 31;
    const int lm   = l >> 2;
    const int lk   = l & 3;
    const int wid  = tid >> 5;
    const int wm   = wid >> 2;
    const int wn   = wid & 3;
    const size_t block_row = (size_t)blockIdx.x * 128;
    const uint32_t* __restrict__ A = g_X0 + block_row * 128;   // 128 words/row
    const uint32_t* __restrict__ B = g_W0T;                    // [kpair][n]

    auto stageA = [&](int s) -> uint32_t (*)[36] {
        return (uint32_t (*)[36])(sm + s * STG_W);
    };
    auto stageB = [&](int s) -> uint32_t (*)[132] {
        return (uint32_t (*)[132])(sm + s * STG_W + AS_W);
    };

    auto prefetch = [&](int chunk) {
        const int s = chunk % 3;
        const int k0 = chunk * 32;                 // word-col base
        uint32_t (*As)[36] = stageA(s);
        uint32_t (*Bs)[132] = stageB(s);
        #pragma unroll
        for (int it = 0; it < 4; it++) {
            int idx = it * 256 + tid;              // 0..1023
            int row = idx >> 3;
            int c4  = idx & 7;
            uint32_t d = smem_u32(&As[row][c4 * 4]);
            const uint32_t* src = A + (size_t)row * 128 + k0 + c4 * 4;
            asm volatile("cp.async.cg.shared.global [%0], [%1], 16;" :: "r"(d), "l"(src));
        }
        #pragma unroll
        for (int it = 0; it < 4; it++) {
            int idx = it * 256 + tid;
            int kk = idx >> 5;
            int n4 = idx & 31;
            uint32_t d = smem_u32(&Bs[kk][n4 * 4]);
            const uint32_t* src = B + (size_t)(k0 + kk) * 128 + n4 * 4;
            asm volatile("cp.async.cg.shared.global [%0], [%1], 16;" :: "r"(d), "l"(src));
        }
        asm volatile("cp.async.commit_group;" ::: "memory");
    };

    float acc[4][4][4];
    #pragma unroll
    for (int i = 0; i < 4; i++)
        #pragma unroll
        for (int j = 0; j < 4; j++)
            #pragma unroll
            for (int c = 0; c < 4; c++) acc[i][j][c] = 0.f;

    prefetch(0);
    prefetch(1);

    #pragma unroll
    for (int ch = 0; ch < 4; ch++) {
        const int s = ch % 3;
        if (ch < 3) {
            asm volatile("cp.async.wait_group 1;" ::: "memory");
        } else {
            asm volatile("cp.async.wait_group 0;" ::: "memory");
        }
        __syncthreads();
        if (ch + 2 < 4) prefetch(ch + 2);   // writes buffer (ch+2)%3 — free

        uint32_t (*As)[36] = stageA(s);
        uint32_t (*Bs)[132] = stageB(s);
        #pragma unroll
        for (int kk = 0; kk < 4; kk++) {           // each kk = k16 (8 word-cols)
            const int k8 = kk * 8;
            uint32_t af[4][4], bf[4][2];
            #pragma unroll
            for (int mt = 0; mt < 4; mt++) {
                int mrow = wm * 64 + mt * 16 + lm;
                af[mt][0] = As[mrow    ][k8 + lk];
                af[mt][1] = As[mrow + 8][k8 + lk];
                af[mt][2] = As[mrow    ][k8 + lk + 4];
                af[mt][3] = As[mrow + 8][k8 + lk + 4];
            }
            #pragma unroll
            for (int nt = 0; nt < 4; nt++) {
                int ncol = wn * 32 + nt * 8 + lm;
                bf[nt][0] = Bs[k8 + lk    ][ncol];
                bf[nt][1] = Bs[k8 + lk + 4][ncol];
            }
            #pragma unroll
            for (int mt = 0; mt < 4; mt++)
                #pragma unroll
                for (int nt = 0; nt < 4; nt++)
                    mma_f16(acc[mt][nt], af[mt][0], af[mt][1], af[mt][2], af[mt][3],
                            bf[nt][0], bf[nt][1]);
        }
    }

    float2* __restrict__ H2 = (float2*)g_H1;      // row stride = 64 float2
    #pragma unroll
    for (int nt = 0; nt < 4; nt++) {
        int col = wn * 32 + nt * 8 + lk * 2;
        float bv0 = g_b0[col], bv1 = g_b0[col + 1];
        #pragma unroll
        for (int mt = 0; mt < 4; mt++) {
            size_t row0 = block_row + wm * 64 + mt * 16 + lm;
            float2 v0 = make_float2(fmaxf(acc[mt][nt][0] + bv0, 0.f),
                                    fmaxf(acc[mt][nt][1] + bv1, 0.f));
            float2 v1 = make_float2(fmaxf(acc[mt][nt][2] + bv0, 0.f),
                                    fmaxf(acc[mt][nt][3] + bv1, 0.f));
            H2[row0 * 64 + (col >> 1)]       = v0;
            H2[(row0 + 8) * 64 + (col >> 1)] = v1;
        }
    }
}

// ---------------- layer-1 fused: gather + mean + tf32 MMA + bias -----------
// (unchanged from R14 — measured fast)
#define G1_AS_W (32 * 260)                 // 8320 words
#define G1_BS_W (256 * 68)                 // 17408 words
#define GEMM1_SM_BYTES ((G1_AS_W + G1_BS_W) * 4)   // 102912

__global__ __launch_bounds__(256) void layer1_fused_kernel(
    const int* __restrict__ nbr1, float* __restrict__ C) {
    extern __shared__ uint32_t sm1[];
    uint32_t (*As)[260] = (uint32_t (*)[260])sm1;
    uint32_t (*Bs)[68]  = (uint32_t (*)[68])(sm1 + G1_AS_W);

    const int tid  = threadIdx.x;
    const int l    = tid & 31;
    const int lane = l;
    const int wid  = tid >> 5;
    const size_t block_row = (size_t)blockIdx.x * 32;

    // --- issue cp.async for full WfT (streams under the gather) ---
    const uint32_t* __restrict__ B = g_WfT;
    #pragma unroll
    for (int it = 0; it < 16; it++) {
        int idx = it * 256 + tid;
        int kk = idx >> 4;
        int n4 = idx & 15;
        uint32_t d = smem_u32(&Bs[kk][n4 * 4]);
        asm volatile("cp.async.cg.shared.global [%0], [%1], 16;"
                     :: "r"(d), "l"(B + (size_t)kk * 64 + n4 * 4));
    }
    asm volatile("cp.async.commit_group;" ::: "memory");

    // --- gather phase: 4 rows per warp, register-batched ---
    const float4* H = (const float4*)g_H1;          // row stride = 32 float4
    const float inv = 1.0f / (float)FANOUT;
    #pragma unroll
    for (int rr = 0; rr < 4; rr++) {
        const int r = wid * 4 + rr;
        const size_t grow = block_row + r;
        int nj = (lane < FANOUT) ? nbr1[grow * FANOUT + lane] : 0;
        int gj[FANOUT];
        #pragma unroll
        for (int j = 0; j < FANOUT; j++) gj[j] = __shfl_sync(0xffffffffu, nj, j);

        float4 s  = __ldg(&H[grow * 32 + lane]);
        float4 n0 = __ldg(&H[(size_t)gj[0] * 32 + lane]);
        float4 n1 = __ldg(&H[(size_t)gj[1] * 32 + lane]);
        float4 n2 = __ldg(&H[(size_t)gj[2] * 32 + lane]);
        float4 n3 = __ldg(&H[(size_t)gj[3] * 32 + lane]);
        float4 n4 = __ldg(&H[(size_t)gj[4] * 32 + lane]);
        float4 n5 = __ldg(&H[(size_t)gj[5] * 32 + lane]);
        float4 n6 = __ldg(&H[(size_t)gj[6] * 32 + lane]);
        float4 n7 = __ldg(&H[(size_t)gj[7] * 32 + lane]);
        float4 t0 = f4add(n0, n1), t1 = f4add(n2, n3);
        float4 t2 = f4add(n4, n5), t3 = f4add(n6, n7);
        float4 acc1 = f4add(f4add(t0, t1), f4add(t2, t3));

        float4 m0 = __ldg(&H[(size_t)gj[8]  * 32 + lane]);
        float4 m1 = __ldg(&H[(size_t)gj[9]  * 32 + lane]);
        float4 m2 = __ldg(&H[(size_t)gj[10] * 32 + lane]);
        float4 m3 = __ldg(&H[(size_t)gj[11] * 32 + lane]);
        float4 m4 = __ldg(&H[(size_t)gj[12] * 32 + lane]);
        float4 m5 = __ldg(&H[(size_t)gj[13] * 32 + lane]);
        float4 m6 = __ldg(&H[(size_t)gj[14] * 32 + lane]);
        float4 m7 = __ldg(&H[(size_t)gj[15] * 32 + lane]);
        float4 u0 = f4add(m0, m1), u1 = f4add(m2, m3);
        float4 u2 = f4add(m4, m5), u3 = f4add(m6, m7);
        float4 acc2 = f4add(f4add(u0, u1), f4add(u2, u3));

        float4 acc = f4add(acc1, acc2);

        uint4 ts, tn;
        ts.x = f2tf32(s.x); ts.y = f2tf32(s.y); ts.z = f2tf32(s.z); ts.w = f2tf32(s.w);
        tn.x = f2tf32(acc.x * inv); tn.y = f2tf32(acc.y * inv);
        tn.z = f2tf32(acc.z * inv); tn.w = f2tf32(acc.w * inv);
        *(uint4*)&As[r][lane * 4]       = ts;
        *(uint4*)&As[r][128 + lane * 4] = tn;
    }

    asm volatile("cp.async.wait_group 0;" ::: "memory");
    __syncthreads();

    // --- MMA phase: 8 warps 2(m) x 4(n), warp tile 16x16, sync-free ---
    const int lm = l >> 2;
    const int lk = l & 3;
    const int wm = wid >> 2;
    const int wn = wid & 3;

    float acc[2][4];
    #pragma unroll
    for (int j = 0; j < 2; j++)
        #pragma unroll
        for (int c = 0; c < 4; c++) acc[j][c] = 0.f;

    const int mrow = wm * 16 + lm;
    #pragma unroll
    for (int k8 = 0; k8 < 256; k8 += 8) {
        uint32_t a0 = As[mrow    ][k8 + lk];
        uint32_t a1 = As[mrow + 8][k8 + lk];
        uint32_t a2 = As[mrow    ][k8 + lk + 4];
        uint32_t a3 = As[mrow + 8][k8 + lk + 4];
        #pragma unroll
        for (int nt = 0; nt < 2; nt++) {
            int ncol = wn * 16 + nt * 8 + lm;
            uint32_t b0 = Bs[k8 + lk    ][ncol];
            uint32_t b1 = Bs[k8 + lk + 4][ncol];
            mma_tf32(acc[nt], a0, a1, a2, a3, b0, b1);
        }
    }

    // epilogue: +bf, write float2
    #pragma unroll
    for (int nt = 0; nt < 2; nt++) {
        int col = wn * 16 + nt * 8 + lk * 2;
        float bv0 = g_bf[col], bv1 = g_bf[col + 1];
        size_t row0 = block_row + wm * 16 + lm;
        float2* c0 = (float2*)(C + row0 * 64 + col);
        float2* c1 = (float2*)(C + (row0 + 8) * 64 + col);
        *c0 = make_float2(acc[nt][0] + bv0, acc[nt][1] + bv1);
        *c1 = make_float2(acc[nt][2] + bv0, acc[nt][3] + bv1);
    }
}

// ---------------- launch ---------------------------------------------------
extern "C" void kernel_launch(void* const* d_in, const int* in_sizes, int n_in,
                              void* d_out, int out_size) {
    const float* emb      = (const float*)d_in[0];
    const float* Ws0      = (const float*)d_in[1];
    const float* bs0      = (const float*)d_in[2];
    const float* Wn0      = (const float*)d_in[3];
    const float* bn0      = (const float*)d_in[4];
    const float* Ws1      = (const float*)d_in[5];
    const float* bs1      = (const float*)d_in[6];
    const float* Wn1      = (const float*)d_in[7];
    const float* bn1      = (const float*)d_in[8];
    const float* Wout     = (const float*)d_in[9];
    const float* bout     = (const float*)d_in[10];
    const int*   in_nodes = (const int*)d_in[11];
    const int*   nbr0     = (const int*)d_in[12];
    const int*   nbr1     = (const int*)d_in[13];
    float* out = (float*)d_out;

    cudaFuncSetAttribute(gemm0_tc_kernel,
                         cudaFuncAttributeMaxDynamicSharedMemorySize, GEMM0_SM_BYTES);
    cudaFuncSetAttribute(layer1_fused_kernel,
                         cudaFuncAttributeMaxDynamicSharedMemorySize, GEMM1_SM_BYTES);

    // layer 0: gather(+fp16 pack) + weight prep in ONE launch, then fp16 GEMM
    gather0_prep_kernel<<<G0_BLOCKS + PREP_BLOCKS, 256>>>(
        emb, in_nodes, nbr0,
        Ws0, bs0, Wn0, bn0, Ws1, bs1, Wn1, bn1, Wout, bout);
    gemm0_tc_kernel<<<N_DST0 / 128, 256, GEMM0_SM_BYTES>>>();

    // layer 1: gather + output GEMM fully fused (one launch)
    layer1_fused_kernel<<<N_DST1 / 32, 256, GEMM1_SM_BYTES>>>(nbr1, out);
}